// round 4
// baseline (speedup 1.0000x reference)
#include <cuda_runtime.h>
#include <cuda_bf16.h>

// ---------------- problem constants ----------------
#define Bb   8
#define Nn   4096
#define Mm   256
#define Dd   256
#define Ii   512
#define Hh   8
#define DH   64
#define BH   (Bb*Hh)           // 64
#define SCALE 0.125f
#define EPS   1e-5f

// ---------------- scratch (device globals; no allocation allowed) ----------------
__device__ float g_posT[Bb*Nn*Dd];          // [B,N,D] transposed pos
__device__ float g_q  [Bb*Nn*Ii];
__device__ float g_k  [Bb*Mm*Ii];
__device__ float g_v1 [Bb*Nn*Ii];
__device__ float g_v2 [Bb*Mm*Ii];
__device__ float g_S  [(size_t)BH*Nn*Mm];   // 268MB
__device__ float g_rmax[BH*Nn];
__device__ float g_rsum[BH*Nn];
__device__ float g_pcmax[8*BH*Mm];
__device__ float g_pcsum[8*BH*Mm];
__device__ float g_cmax[BH*Mm];
__device__ float g_csum[BH*Mm];
__device__ float g_of [Bb*Nn*Ii];           // merged attn out (feat path)
__device__ float g_ocp[(size_t)8*BH*Mm*DH]; // split-K partials for center attn out
__device__ float g_oc [Bb*Mm*Ii];
__device__ float g_pre [Bb*Nn*Dd];          // pre-LN feat / relu hidden (reused)
__device__ float g_prec[Bb*Mm*Dd];
__device__ float g_xf [Bb*Nn*Dd];           // post-LN feat
__device__ float g_xc [Bb*Mm*Dd];
__device__ float g_hf [Bb*Nn*Dd];           // relu hidden (feat)
__device__ float g_hc [Bb*Mm*Dd];

// ---------------- 16-step 4x4 micro-kernel over 64-wide shared tiles ----------------
__device__ __forceinline__ void mm16(const float (*As)[64], const float (*Bs)[64],
                                     float acc[4][4], int ty, int tx) {
#pragma unroll
    for (int k = 0; k < 16; k++) {
        float4 a = *(const float4*)&As[k][ty*4];
        float4 b = *(const float4*)&Bs[k][tx*4];
        acc[0][0] += a.x*b.x; acc[0][1] += a.x*b.y; acc[0][2] += a.x*b.z; acc[0][3] += a.x*b.w;
        acc[1][0] += a.y*b.x; acc[1][1] += a.y*b.y; acc[1][2] += a.y*b.z; acc[1][3] += a.y*b.w;
        acc[2][0] += a.z*b.x; acc[2][1] += a.z*b.y; acc[2][2] += a.z*b.z; acc[2][3] += a.z*b.w;
        acc[3][0] += a.w*b.x; acc[3][1] += a.w*b.y; acc[3][2] += a.w*b.z; acc[3][3] += a.w*b.w;
    }
}

// ---------------- pos transpose: [B, D, N] -> [B, N, D] ----------------
__global__ void __launch_bounds__(1024)
transpose_pos(const float* __restrict__ pos, float* __restrict__ posT) {
    __shared__ float t[32][33];
    int b = blockIdx.z;
    int c0 = blockIdx.x * 32, n0 = blockIdx.y * 32;
    int tx = threadIdx.x, ty = threadIdx.y;
    t[ty][tx] = pos[(size_t)b*Dd*Nn + (size_t)(c0+ty)*Nn + n0 + tx];
    __syncthreads();
    posT[(size_t)b*Nn*Dd + (size_t)(n0+ty)*Dd + c0 + tx] = t[tx][ty];
}

// ---------------- generic row-major GEMM: C[Mr,Nc] = op(A)[Mr,K] @ B[K,Nc] ----------------
// AMODE: 0 plain, 1 A+A2 elementwise
// EPI:   0 none, 1 +Res, 2 relu, 3 +bias[col]+Res
template<int AMODE, int EPI>
__global__ void __launch_bounds__(256)
gemm_rrr(const float* __restrict__ A, const float* __restrict__ A2,
         const float* __restrict__ Bm, const float* __restrict__ Res,
         const float* __restrict__ bias, float* __restrict__ C,
         int Mr, int K, int Nc) {
    __shared__ float As[16][64];
    __shared__ float Bs[16][64];
    int t = threadIdx.x;
    int tx = t & 15, ty = t >> 4;
    int row0 = blockIdx.y * 64, col0 = blockIdx.x * 64;
    float acc[4][4] = {};
    int la_r = t >> 2, la_c = (t & 3) * 4;
    int lb_r = t >> 4, lb_c = (t & 15) * 4;
    const float* Aptr  = A  + (size_t)(row0 + la_r) * K + la_c;
    const float* A2ptr = A2 + (size_t)(row0 + la_r) * K + la_c;
    const float* Bptr  = Bm + (size_t)lb_r * Nc + col0 + lb_c;
    for (int k0 = 0; k0 < K; k0 += 16) {
        float4 av = *(const float4*)(Aptr + k0);
        if (AMODE == 1) {
            float4 a2 = *(const float4*)(A2ptr + k0);
            av.x += a2.x; av.y += a2.y; av.z += a2.z; av.w += a2.w;
        }
        As[la_c+0][la_r] = av.x; As[la_c+1][la_r] = av.y;
        As[la_c+2][la_r] = av.z; As[la_c+3][la_r] = av.w;
        *(float4*)&Bs[lb_r][lb_c] = *(const float4*)(Bptr + (size_t)k0 * Nc);
        __syncthreads();
        mm16(As, Bs, acc, ty, tx);
        __syncthreads();
    }
#pragma unroll
    for (int i = 0; i < 4; i++) {
        int r = row0 + ty*4 + i;
#pragma unroll
        for (int j = 0; j < 4; j++) {
            int c = col0 + tx*4 + j;
            float v = acc[i][j];
            if (EPI == 1) v += Res[(size_t)r*Nc + c];
            if (EPI == 2) v = fmaxf(v, 0.f);
            if (EPI == 3) v += bias[c] + Res[(size_t)r*Nc + c];
            C[(size_t)r*Nc + c] = v;
        }
    }
}

// ---------------- S[b,h,n,m] = SCALE * q_h[n,:] . k_h[m,:] ----------------
__global__ void __launch_bounds__(256)
attn_scores(const float* __restrict__ q, const float* __restrict__ kk,
            float* __restrict__ S) {
    __shared__ float As[16][64];  // [k][n]
    __shared__ float Bs[16][64];  // [k][m]
    int bh = blockIdx.z; int b = bh >> 3, h = bh & 7;
    int n0 = blockIdx.y * 64, m0 = blockIdx.x * 64;
    int t = threadIdx.x, tx = t & 15, ty = t >> 4;
    float acc[4][4] = {};
    int la_r = t >> 2, la_c = (t & 3) * 4;
    const float* qptr = q  + (size_t)(b*Nn + n0 + la_r) * Ii + h*DH + la_c;
    const float* kptr = kk + (size_t)(b*Mm + m0 + la_r) * Ii + h*DH + la_c;
    for (int k0 = 0; k0 < DH; k0 += 16) {
        float4 av = *(const float4*)(qptr + k0);
        As[la_c+0][la_r] = av.x; As[la_c+1][la_r] = av.y;
        As[la_c+2][la_r] = av.z; As[la_c+3][la_r] = av.w;
        float4 bv = *(const float4*)(kptr + k0);
        Bs[la_c+0][la_r] = bv.x; Bs[la_c+1][la_r] = bv.y;
        Bs[la_c+2][la_r] = bv.z; Bs[la_c+3][la_r] = bv.w;
        __syncthreads();
        mm16(As, Bs, acc, ty, tx);
        __syncthreads();
    }
    float* Sp = S + ((size_t)bh*Nn + n0)*Mm + m0;
#pragma unroll
    for (int i = 0; i < 4; i++)
#pragma unroll
        for (int j = 0; j < 4; j++)
            Sp[(size_t)(ty*4+i)*Mm + tx*4+j] = acc[i][j] * SCALE;
}

// ---------------- per-row (n) softmax stats over m ----------------
__global__ void __launch_bounds__(256)
row_stats(const float* __restrict__ S, float* __restrict__ rmax,
          float* __restrict__ rsum) {
    int warp = threadIdx.x >> 5, lane = threadIdx.x & 31;
    size_t row = (size_t)blockIdx.x * 8 + warp;
    const float* p = S + row * Mm;
    float v[8], mx = -1e30f;
#pragma unroll
    for (int i = 0; i < 8; i++) { v[i] = p[lane + i*32]; mx = fmaxf(mx, v[i]); }
#pragma unroll
    for (int o = 16; o; o >>= 1) mx = fmaxf(mx, __shfl_xor_sync(0xffffffffu, mx, o));
    float s = 0.f;
#pragma unroll
    for (int i = 0; i < 8; i++) s += __expf(v[i] - mx);
#pragma unroll
    for (int o = 16; o; o >>= 1) s += __shfl_xor_sync(0xffffffffu, s, o);
    if (lane == 0) { rmax[row] = mx; rsum[row] = s; }
}

// ---------------- per-column (m) stats over n, split in 8 n-chunks ----------------
__global__ void __launch_bounds__(256)
col_stats_part(const float* __restrict__ S, float* __restrict__ pmax,
               float* __restrict__ psum) {
    int bh = blockIdx.x, sp = blockIdx.y, m = threadIdx.x;
    const float* p = S + ((size_t)bh*Nn + (size_t)sp*512)*Mm + m;
    float mx = -1e30f, s = 0.f;
    for (int n = 0; n < 512; n++) {
        float v = p[(size_t)n * Mm];
        if (v > mx) { s = s * __expf(mx - v) + 1.f; mx = v; }
        else        { s += __expf(v - mx); }
    }
    pmax[(sp*BH + bh)*Mm + m] = mx;
    psum[(sp*BH + bh)*Mm + m] = s;
}

__global__ void __launch_bounds__(256)
col_stats_combine(const float* __restrict__ pmax, const float* __restrict__ psum,
                  float* __restrict__ cmax, float* __restrict__ csum) {
    int bh = blockIdx.x, m = threadIdx.x;
    float mx = -1e30f;
#pragma unroll
    for (int sp = 0; sp < 8; sp++) mx = fmaxf(mx, pmax[(sp*BH + bh)*Mm + m]);
    float s = 0.f;
#pragma unroll
    for (int sp = 0; sp < 8; sp++) s += psum[(sp*BH + bh)*Mm + m] * __expf(pmax[(sp*BH + bh)*Mm + m] - mx);
    cmax[bh*Mm + m] = mx;
    csum[bh*Mm + m] = s;
}

// ---------------- out_feat attn: O[n,d] = (exp(S-rmax) @ v2_h) / rsum ----------------
__global__ void __launch_bounds__(256)
attn_out_feat(const float* __restrict__ S, const float* __restrict__ v2,
              const float* __restrict__ rmax, const float* __restrict__ rsum,
              float* __restrict__ of) {
    __shared__ float As[16][64];  // [m][n]  (exp'd)
    __shared__ float Bs[16][64];  // [m][d]
    int bh = blockIdx.y; int b = bh >> 3, h = bh & 7;
    int n0 = blockIdx.x * 64;
    int t = threadIdx.x, tx = t & 15, ty = t >> 4;
    float acc[4][4] = {};
    int la_r = t >> 2, la_c = (t & 3) * 4;
    const float* Sp = S + ((size_t)bh*Nn + n0 + la_r) * Mm + la_c;
    float lmx = rmax[(size_t)bh*Nn + n0 + la_r];
    int lb_k = t >> 4, lb_d = (t & 15) * 4;
    const float* vp = v2 + (size_t)(b*Mm) * Ii + h*DH + lb_d;
    for (int m0 = 0; m0 < Mm; m0 += 16) {
        float4 av = *(const float4*)(Sp + m0);
        As[la_c+0][la_r] = __expf(av.x - lmx);
        As[la_c+1][la_r] = __expf(av.y - lmx);
        As[la_c+2][la_r] = __expf(av.z - lmx);
        As[la_c+3][la_r] = __expf(av.w - lmx);
        *(float4*)&Bs[lb_k][lb_d] = *(const float4*)(vp + (size_t)(m0 + lb_k) * Ii);
        __syncthreads();
        mm16(As, Bs, acc, ty, tx);
        __syncthreads();
    }
#pragma unroll
    for (int i = 0; i < 4; i++) {
        int n = n0 + ty*4 + i;
        float rinv = 1.f / rsum[(size_t)bh*Nn + n];
#pragma unroll
        for (int j = 0; j < 4; j++)
            of[(size_t)(b*Nn + n) * Ii + h*DH + tx*4 + j] = acc[i][j] * rinv;
    }
}

// ---------------- out_center attn (split-K over n): partial[m,d] = sum_n exp(S-cmax[m]) * v1 ----------------
__global__ void __launch_bounds__(256)
attn_out_center_part(const float* __restrict__ S, const float* __restrict__ v1,
                     const float* __restrict__ cmax, float* __restrict__ ocp) {
    __shared__ float Ss[16][256];
    __shared__ float Vs[16][64];
    __shared__ float cmx[256];
    int bh = blockIdx.x, sp = blockIdx.y; int b = bh >> 3, h = bh & 7;
    int t = threadIdx.x;
    cmx[t] = cmax[bh*Mm + t];
    __syncthreads();
    int tm = (t & 31) * 8;    // m-base (32 groups * 8 = 256)
    int td = (t >> 5) * 8;    // d-base (8 groups * 8 = 64)
    float acc[8][8] = {};
    int l_r = t >> 4, l_c = (t & 15) * 16;
    int lv_r = t >> 4, lv_c = (t & 15) * 4;
    int nbase = sp * 512;
    for (int n0 = 0; n0 < 512; n0 += 16) {
        const float* Sp = S + ((size_t)bh*Nn + nbase + n0 + l_r) * Mm + l_c;
#pragma unroll
        for (int i = 0; i < 16; i += 4) {
            float4 v = *(const float4*)(Sp + i);
            Ss[l_r][l_c+i+0] = __expf(v.x - cmx[l_c+i+0]);
            Ss[l_r][l_c+i+1] = __expf(v.y - cmx[l_c+i+1]);
            Ss[l_r][l_c+i+2] = __expf(v.z - cmx[l_c+i+2]);
            Ss[l_r][l_c+i+3] = __expf(v.w - cmx[l_c+i+3]);
        }
        *(float4*)&Vs[lv_r][lv_c] =
            *(const float4*)(v1 + (size_t)(b*Nn + nbase + n0 + lv_r) * Ii + h*DH + lv_c);
        __syncthreads();
#pragma unroll
        for (int kk = 0; kk < 16; kk++) {
            float mr[8], dr[8];
            *(float4*)&mr[0] = *(const float4*)&Ss[kk][tm];
            *(float4*)&mr[4] = *(const float4*)&Ss[kk][tm+4];
            *(float4*)&dr[0] = *(const float4*)&Vs[kk][td];
            *(float4*)&dr[4] = *(const float4*)&Vs[kk][td+4];
#pragma unroll
            for (int i = 0; i < 8; i++)
#pragma unroll
                for (int j = 0; j < 8; j++)
                    acc[i][j] += mr[i] * dr[j];
        }
        __syncthreads();
    }
    float* op = ocp + ((size_t)(sp*BH + bh)) * Mm * DH;
#pragma unroll
    for (int i = 0; i < 8; i++)
#pragma unroll
        for (int j = 0; j < 8; j++)
            op[(size_t)(tm+i)*DH + td + j] = acc[i][j];
}

__global__ void __launch_bounds__(256)
oc_combine(const float* __restrict__ ocp, const float* __restrict__ csum,
           float* __restrict__ oc) {
    size_t idx = (size_t)blockIdx.x * 256 + threadIdx.x;   // over BH*256*64
    int bh = (int)(idx >> 14);
    int r = (int)(idx & 16383);
    int m = r >> 6, d = r & 63;
    float s = 0.f;
#pragma unroll
    for (int sp = 0; sp < 8; sp++)
        s += ocp[((size_t)(sp*BH + bh)) * Mm * DH + (size_t)m*DH + d];
    int b = bh >> 3, h = bh & 7;
    oc[(size_t)(b*Mm + m) * Ii + h*DH + d] = s / csum[bh*Mm + m];
}

// ---------------- layernorm over last dim (256) ----------------
__global__ void __launch_bounds__(256)
layernorm(const float* __restrict__ x, const float* __restrict__ w,
          const float* __restrict__ b, float* __restrict__ y) {
    __shared__ float red[256];
    __shared__ float stat[2];
    int r = blockIdx.x, t = threadIdx.x;
    float v = x[(size_t)r*Dd + t];
    red[t] = v; __syncthreads();
    for (int o = 128; o; o >>= 1) { if (t < o) red[t] += red[t+o]; __syncthreads(); }
    if (t == 0) stat[0] = red[0] * (1.f/Dd);
    __syncthreads();
    float mu = stat[0];
    float dv = v - mu;
    red[t] = dv * dv; __syncthreads();
    for (int o = 128; o; o >>= 1) { if (t < o) red[t] += red[t+o]; __syncthreads(); }
    if (t == 0) stat[1] = rsqrtf(red[0] * (1.f/Dd) + EPS);
    __syncthreads();
    y[(size_t)r*Dd + t] = dv * stat[1] * w[t] + b[t];
}

// ---------------- launch ----------------
extern "C" void kernel_launch(void* const* d_in, const int* in_sizes, int n_in,
                              void* d_out, int out_size) {
    const float* feat       = (const float*)d_in[0];
    const float* center     = (const float*)d_in[1];
    const float* pos        = (const float*)d_in[2];
    const float* center_pos = (const float*)d_in[3];
    const float* Wq  = (const float*)d_in[4];
    const float* Wk  = (const float*)d_in[5];
    const float* Wv1 = (const float*)d_in[6];
    const float* Wv2 = (const float*)d_in[7];
    const float* Wo1 = (const float*)d_in[8];
    const float* Wo2 = (const float*)d_in[9];
    const float* ln1_w = (const float*)d_in[10];
    const float* ln1_b = (const float*)d_in[11];
    const float* ln2_w = (const float*)d_in[12];
    const float* ln2_b = (const float*)d_in[13];
    const float* f1W1 = (const float*)d_in[14];
    const float* f1W2 = (const float*)d_in[15];
    const float* f1b2 = (const float*)d_in[16];
    const float* f2W1 = (const float*)d_in[17];
    const float* f2W2 = (const float*)d_in[18];
    const float* f2b2 = (const float*)d_in[19];

    float* out_feat   = (float*)d_out;
    float* out_center = (float*)d_out + (size_t)Bb*Nn*Dd;

    float *posT, *q, *k, *v1, *v2, *S, *rmax, *rsum, *pcmax, *pcsum, *cmaxp, *csump;
    float *of, *ocp, *oc, *pre, *prec, *xf, *xc, *hf, *hc;
    cudaGetSymbolAddress((void**)&posT, g_posT);
    cudaGetSymbolAddress((void**)&q,    g_q);
    cudaGetSymbolAddress((void**)&k,    g_k);
    cudaGetSymbolAddress((void**)&v1,   g_v1);
    cudaGetSymbolAddress((void**)&v2,   g_v2);
    cudaGetSymbolAddress((void**)&S,    g_S);
    cudaGetSymbolAddress((void**)&rmax, g_rmax);
    cudaGetSymbolAddress((void**)&rsum, g_rsum);
    cudaGetSymbolAddress((void**)&pcmax,g_pcmax);
    cudaGetSymbolAddress((void**)&pcsum,g_pcsum);
    cudaGetSymbolAddress((void**)&cmaxp,g_cmax);
    cudaGetSymbolAddress((void**)&csump,g_csum);
    cudaGetSymbolAddress((void**)&of,   g_of);
    cudaGetSymbolAddress((void**)&ocp,  g_ocp);
    cudaGetSymbolAddress((void**)&oc,   g_oc);
    cudaGetSymbolAddress((void**)&pre,  g_pre);
    cudaGetSymbolAddress((void**)&prec, g_prec);
    cudaGetSymbolAddress((void**)&xf,   g_xf);
    cudaGetSymbolAddress((void**)&xc,   g_xc);
    cudaGetSymbolAddress((void**)&hf,   g_hf);
    cudaGetSymbolAddress((void**)&hc,   g_hc);

    // 1) pos transpose
    transpose_pos<<<dim3(Dd/32, Nn/32, Bb), dim3(32,32)>>>(pos, posT);

    // 2) projections
    gemm_rrr<1,0><<<dim3(Ii/64, Bb*Nn/64), 256>>>(feat, posT, Wq, nullptr, nullptr, q, Bb*Nn, Dd, Ii);
    gemm_rrr<0,0><<<dim3(Ii/64, Bb*Nn/64), 256>>>(feat, nullptr, Wv1, nullptr, nullptr, v1, Bb*Nn, Dd, Ii);
    gemm_rrr<1,0><<<dim3(Ii/64, Bb*Mm/64), 256>>>(center, center_pos, Wk, nullptr, nullptr, k, Bb*Mm, Dd, Ii);
    gemm_rrr<0,0><<<dim3(Ii/64, Bb*Mm/64), 256>>>(center, nullptr, Wv2, nullptr, nullptr, v2, Bb*Mm, Dd, Ii);

    // 3) logits + softmax stats
    attn_scores<<<dim3(Mm/64, Nn/64, BH), 256>>>(q, k, S);
    row_stats<<<BH*Nn/8, 256>>>(S, rmax, rsum);
    col_stats_part<<<dim3(BH, 8), 256>>>(S, pcmax, pcsum);
    col_stats_combine<<<BH, 256>>>(pcmax, pcsum, cmaxp, csump);

    // 4) attention applies
    attn_out_feat<<<dim3(Nn/64, BH), 256>>>(S, v2, rmax, rsum, of);
    attn_out_center_part<<<dim3(BH, 8), 256>>>(S, v1, cmaxp, ocp);
    oc_combine<<<BH*Mm*DH/256, 256>>>(ocp, csump, oc);

    // 5) feat path: Wo1 + residual, LN, FFN
    gemm_rrr<0,1><<<dim3(Dd/64, Bb*Nn/64), 256>>>(of, nullptr, Wo1, feat, nullptr, pre, Bb*Nn, Ii, Dd);
    layernorm<<<Bb*Nn, 256>>>(pre, ln1_w, ln1_b, xf);
    gemm_rrr<0,2><<<dim3(Dd/64, Bb*Nn/64), 256>>>(xf, nullptr, f1W1, nullptr, nullptr, hf, Bb*Nn, Dd, Dd);
    gemm_rrr<0,3><<<dim3(Dd/64, Bb*Nn/64), 256>>>(hf, nullptr, f1W2, xf, f1b2, out_feat, Bb*Nn, Dd, Dd);

    // 6) center path
    gemm_rrr<0,1><<<dim3(Dd/64, Bb*Mm/64), 256>>>(oc, nullptr, Wo2, center, nullptr, prec, Bb*Mm, Ii, Dd);
    layernorm<<<Bb*Mm, 256>>>(prec, ln2_w, ln2_b, xc);
    gemm_rrr<0,2><<<dim3(Dd/64, Bb*Mm/64), 256>>>(xc, nullptr, f2W1, nullptr, nullptr, hc, Bb*Mm, Dd, Dd);
    gemm_rrr<0,3><<<dim3(Dd/64, Bb*Mm/64), 256>>>(hc, nullptr, f2W2, xc, f2b2, out_center, Bb*Mm, Dd, Dd);
}

// round 10
// speedup vs baseline: 1.2950x; 1.2950x over previous
#include <cuda_runtime.h>

// ---------------- problem constants ----------------
#define Bb   8
#define Nn   4096
#define Mm   256
#define Dd   256
#define Ii   512
#define DH   64
#define BH   64
#define SCALE 0.125f
#define EPS   1e-5f

// ---------------- scratch ----------------
__device__ float g_posT[Bb*Nn*Dd];
__device__ float g_q  [Bb*Nn*Ii];
__device__ float g_k  [Bb*Mm*Ii];
__device__ float g_v1 [Bb*Nn*Ii];
__device__ float g_v2 [Bb*Mm*Ii];
__device__ float g_E  [(size_t)BH*Nn*Mm];     // exp(S - rowmax)
__device__ float g_f  [BH*Nn];                // exp(rowmax)
__device__ float g_rsum[BH*Nn];
__device__ float g_pcsum[32*BH*Mm];
__device__ float g_csum[BH*Mm];
__device__ float g_of [Bb*Nn*Ii];
__device__ float g_ocp[(size_t)8*BH*Mm*DH];
__device__ float g_oc [Bb*Mm*Ii];
__device__ float g_pre [Bb*Nn*Dd];
__device__ float g_prec[Bb*Mm*Dd];
__device__ float g_xf [Bb*Nn*Dd];
__device__ float g_xc [Bb*Mm*Dd];
__device__ float g_hf [Bb*Nn*Dd];
__device__ float g_hc [Bb*Mm*Dd];

// ---------------- pos transpose: [B, D, N] -> [B, N, D] ----------------
__global__ void __launch_bounds__(1024)
transpose_pos(const float* __restrict__ pos, float* __restrict__ posT) {
    __shared__ float t[32][33];
    int b = blockIdx.z;
    int c0 = blockIdx.x * 32, n0 = blockIdx.y * 32;
    int tx = threadIdx.x, ty = threadIdx.y;
    t[ty][tx] = pos[(size_t)b*Dd*Nn + (size_t)(c0+ty)*Nn + n0 + tx];
    __syncthreads();
    posT[(size_t)b*Nn*Dd + (size_t)(n0+ty)*Dd + c0 + tx] = t[tx][ty];
}

// ---------------- 128x128 GEMM, 8x8 micro, reg-prefetch, C = op(A)@B ----------------
// AMODE: 0 plain, 1 A+A2.  EPI: 0 none, 1 +Res, 2 relu, 3 +bias+Res
template<int AMODE, int EPI>
__global__ void __launch_bounds__(256, 2)
gemm128(const float* __restrict__ A, const float* __restrict__ A2,
        const float* __restrict__ Bm, const float* __restrict__ Res,
        const float* __restrict__ bias, float* __restrict__ C,
        int Mr, int K, int Nc) {
    __shared__ float As[16][128];
    __shared__ float Bs[16][128];
    int t = threadIdx.x;
    int tx = t & 15, ty = t >> 4;
    int row0 = blockIdx.y * 128, col0 = blockIdx.x * 128;
    float acc[8][8] = {};

    int ar  = t >> 1;           // 0..127
    int akc = (t & 1) * 8;      // 0 / 8
    const float* Ap  = A  + (size_t)(row0 + ar) * K + akc;
    const float* A2p = A2 + (size_t)(row0 + ar) * K + akc;
    int br = t >> 4;            // 0..15
    int bc = (t & 15) * 8;
    const float* Bp = Bm + (size_t)br * Nc + col0 + bc;

    float4 pa0 = *(const float4*)(Ap);
    float4 pa1 = *(const float4*)(Ap + 4);
    if (AMODE) {
        float4 q0 = *(const float4*)(A2p), q1 = *(const float4*)(A2p + 4);
        pa0.x+=q0.x; pa0.y+=q0.y; pa0.z+=q0.z; pa0.w+=q0.w;
        pa1.x+=q1.x; pa1.y+=q1.y; pa1.z+=q1.z; pa1.w+=q1.w;
    }
    float4 pb0 = *(const float4*)(Bp);
    float4 pb1 = *(const float4*)(Bp + 4);

    for (int kc = 0; kc < K; kc += 16) {
        As[akc+0][ar]=pa0.x; As[akc+1][ar]=pa0.y; As[akc+2][ar]=pa0.z; As[akc+3][ar]=pa0.w;
        As[akc+4][ar]=pa1.x; As[akc+5][ar]=pa1.y; As[akc+6][ar]=pa1.z; As[akc+7][ar]=pa1.w;
        *(float4*)&Bs[br][bc]   = pb0;
        *(float4*)&Bs[br][bc+4] = pb1;
        __syncthreads();
        if (kc + 16 < K) {
            pa0 = *(const float4*)(Ap + kc + 16);
            pa1 = *(const float4*)(Ap + kc + 20);
            if (AMODE) {
                float4 q0 = *(const float4*)(A2p + kc + 16), q1 = *(const float4*)(A2p + kc + 20);
                pa0.x+=q0.x; pa0.y+=q0.y; pa0.z+=q0.z; pa0.w+=q0.w;
                pa1.x+=q1.x; pa1.y+=q1.y; pa1.z+=q1.z; pa1.w+=q1.w;
            }
            pb0 = *(const float4*)(Bp + (size_t)(kc + 16) * Nc);
            pb1 = *(const float4*)(Bp + (size_t)(kc + 16) * Nc + 4);
        }
#pragma unroll
        for (int k = 0; k < 16; k++) {
            float4 a0 = *(const float4*)&As[k][ty*4];
            float4 a1 = *(const float4*)&As[k][64+ty*4];
            float4 b0 = *(const float4*)&Bs[k][tx*4];
            float4 b1 = *(const float4*)&Bs[k][64+tx*4];
            float av[8] = {a0.x,a0.y,a0.z,a0.w,a1.x,a1.y,a1.z,a1.w};
            float bv[8] = {b0.x,b0.y,b0.z,b0.w,b1.x,b1.y,b1.z,b1.w};
#pragma unroll
            for (int i = 0; i < 8; i++)
#pragma unroll
                for (int j = 0; j < 8; j++)
                    acc[i][j] += av[i] * bv[j];
        }
        __syncthreads();
    }

#pragma unroll
    for (int i = 0; i < 8; i++) {
        int r = row0 + (i < 4 ? ty*4 + i : 64 + ty*4 + i - 4);
#pragma unroll
        for (int jh = 0; jh < 2; jh++) {
            int c = col0 + jh*64 + tx*4;
            float4 v = { acc[i][jh*4+0], acc[i][jh*4+1], acc[i][jh*4+2], acc[i][jh*4+3] };
            if (EPI == 1 || EPI == 3) {
                float4 rv = *(const float4*)(Res + (size_t)r*Nc + c);
                v.x += rv.x; v.y += rv.y; v.z += rv.z; v.w += rv.w;
            }
            if (EPI == 3) {
                float4 bb = *(const float4*)(bias + c);
                v.x += bb.x; v.y += bb.y; v.z += bb.z; v.w += bb.w;
            }
            if (EPI == 2) {
                v.x = fmaxf(v.x, 0.f); v.y = fmaxf(v.y, 0.f);
                v.z = fmaxf(v.z, 0.f); v.w = fmaxf(v.w, 0.f);
            }
            *(float4*)(C + (size_t)r*Nc + c) = v;
        }
    }
}

// ---------------- fused scores: E=exp(S-rmax), f=exp(rmax), rsum, col partial sums ----------------
// tile: 128 n-rows x 256 m-cols, K=64. 512 threads = 16 warps; warp wy owns rows wy*8..+7,
// lane tx owns cols {tx*4..+3, 128+tx*4..+3}.
__global__ void __launch_bounds__(512, 1)
attn_scores_fused(const float* __restrict__ q, const float* __restrict__ kk,
                  float* __restrict__ E, float* __restrict__ frow,
                  float* __restrict__ rsum, float* __restrict__ pcsum) {
    __shared__ float As[16][128];
    __shared__ float Bs[16][256];
    int bh = blockIdx.y, b = bh >> 3, h = bh & 7;
    int n0 = blockIdx.x * 128;
    int t = threadIdx.x, tx = t & 31, wy = t >> 5;
    float acc[8][8] = {};

    int ar  = t >> 2, akc = (t & 3) * 4;          // q loads: 128 rows x 4 k
    const float* qp = q + (size_t)(b*Nn + n0 + ar) * Ii + h*DH + akc;
    int br  = t >> 1, bkc = (t & 1) * 8;          // k loads: 256 rows x 8 k
    const float* kp = kk + (size_t)(b*Mm + br) * Ii + h*DH + bkc;

    float4 pa = *(const float4*)(qp);
    float4 pb0 = *(const float4*)(kp);
    float4 pb1 = *(const float4*)(kp + 4);

    for (int kc = 0; kc < DH; kc += 16) {
        As[akc+0][ar]=pa.x; As[akc+1][ar]=pa.y; As[akc+2][ar]=pa.z; As[akc+3][ar]=pa.w;
        Bs[bkc+0][br]=pb0.x; Bs[bkc+1][br]=pb0.y; Bs[bkc+2][br]=pb0.z; Bs[bkc+3][br]=pb0.w;
        Bs[bkc+4][br]=pb1.x; Bs[bkc+5][br]=pb1.y; Bs[bkc+6][br]=pb1.z; Bs[bkc+7][br]=pb1.w;
        __syncthreads();
        if (kc + 16 < DH) {
            pa  = *(const float4*)(qp + kc + 16);
            pb0 = *(const float4*)(kp + kc + 16);
            pb1 = *(const float4*)(kp + kc + 20);
        }
#pragma unroll
        for (int k = 0; k < 16; k++) {
            float4 a0 = *(const float4*)&As[k][wy*8];
            float4 a1 = *(const float4*)&As[k][wy*8+4];
            float4 b0 = *(const float4*)&Bs[k][tx*4];
            float4 b1 = *(const float4*)&Bs[k][128+tx*4];
            float av[8] = {a0.x,a0.y,a0.z,a0.w,a1.x,a1.y,a1.z,a1.w};
            float bv[8] = {b0.x,b0.y,b0.z,b0.w,b1.x,b1.y,b1.z,b1.w};
#pragma unroll
            for (int i = 0; i < 8; i++)
#pragma unroll
                for (int j = 0; j < 8; j++)
                    acc[i][j] += av[i] * bv[j];
        }
        __syncthreads();
    }

    float colp[8] = {};
    float* Ebase = E + (size_t)bh * Nn * Mm;
#pragma unroll
    for (int i = 0; i < 8; i++) {
        int n = n0 + wy*8 + i;
        float mx = -1e30f;
#pragma unroll
        for (int j = 0; j < 8; j++) { acc[i][j] *= SCALE; mx = fmaxf(mx, acc[i][j]); }
#pragma unroll
        for (int o = 16; o; o >>= 1) mx = fmaxf(mx, __shfl_xor_sync(0xffffffffu, mx, o));
        float s = 0.f;
#pragma unroll
        for (int j = 0; j < 8; j++) { acc[i][j] = __expf(acc[i][j] - mx); s += acc[i][j]; }
#pragma unroll
        for (int o = 16; o; o >>= 1) s += __shfl_xor_sync(0xffffffffu, s, o);
        float fi = __expf(mx);
        if (tx == 0) { frow[(size_t)bh*Nn + n] = fi; rsum[(size_t)bh*Nn + n] = s; }
#pragma unroll
        for (int j = 0; j < 8; j++) colp[j] += acc[i][j] * fi;
        float* Ep = Ebase + (size_t)n * Mm;
        float4 e0 = {acc[i][0], acc[i][1], acc[i][2], acc[i][3]};
        float4 e1 = {acc[i][4], acc[i][5], acc[i][6], acc[i][7]};
        *(float4*)(Ep + tx*4)       = e0;
        *(float4*)(Ep + 128 + tx*4) = e1;
    }

    // column partial sums: reduce over 16 warps via smem (reuse Bs: 16x256 floats)
    float* red = &Bs[0][0];
    __syncthreads();
#pragma unroll
    for (int j = 0; j < 8; j++) {
        int col = (j < 4) ? tx*4 + j : 128 + tx*4 + (j - 4);
        red[wy*256 + col] = colp[j];
    }
    __syncthreads();
    if (t < 256) {
        float s = 0.f;
#pragma unroll
        for (int w = 0; w < 16; w++) s += red[w*256 + t];
        pcsum[((size_t)blockIdx.x * BH + bh) * Mm + t] = s;
    }
}

__global__ void __launch_bounds__(256)
csum_combine(const float* __restrict__ pcsum, float* __restrict__ csum) {
    int bh = blockIdx.x, m = threadIdx.x;
    float s = 0.f;
#pragma unroll
    for (int p = 0; p < 32; p++) s += pcsum[((size_t)p*BH + bh) * Mm + m];
    csum[bh*Mm + m] = s;
}

// ---------------- out_feat = (E @ v2) / rsum  (no exp) ----------------
// tile 128 n x 64 d; 256 threads; acc 8x4 (rows split-halves)
__global__ void __launch_bounds__(256, 2)
attn_apply_feat(const float* __restrict__ E, const float* __restrict__ v2,
                const float* __restrict__ rsum, float* __restrict__ of) {
    __shared__ float Es[16][128];
    __shared__ float Vs[16][64];
    int bh = blockIdx.y, b = bh >> 3, h = bh & 7;
    int n0 = blockIdx.x * 128;
    int t = threadIdx.x, tx = t & 15, ty = t >> 4;
    float acc[8][4] = {};

    int er = t >> 1, emc = (t & 1) * 8;
    const float* Ep = E + ((size_t)bh*Nn + n0 + er) * Mm + emc;
    int vr = t >> 4, vc = (t & 15) * 4;
    const float* Vp = v2 + (size_t)(b*Mm + vr) * Ii + h*DH + vc;

    float4 pe0 = *(const float4*)(Ep);
    float4 pe1 = *(const float4*)(Ep + 4);
    float4 pv  = *(const float4*)(Vp);

    for (int mc = 0; mc < Mm; mc += 16) {
        Es[emc+0][er]=pe0.x; Es[emc+1][er]=pe0.y; Es[emc+2][er]=pe0.z; Es[emc+3][er]=pe0.w;
        Es[emc+4][er]=pe1.x; Es[emc+5][er]=pe1.y; Es[emc+6][er]=pe1.z; Es[emc+7][er]=pe1.w;
        *(float4*)&Vs[vr][vc] = pv;
        __syncthreads();
        if (mc + 16 < Mm) {
            pe0 = *(const float4*)(Ep + mc + 16);
            pe1 = *(const float4*)(Ep + mc + 20);
            pv  = *(const float4*)(Vp + (size_t)(mc + 16) * Ii);
        }
#pragma unroll
        for (int k = 0; k < 16; k++) {
            float4 a0 = *(const float4*)&Es[k][ty*4];
            float4 a1 = *(const float4*)&Es[k][64+ty*4];
            float4 bv = *(const float4*)&Vs[k][tx*4];
            float av[8] = {a0.x,a0.y,a0.z,a0.w,a1.x,a1.y,a1.z,a1.w};
#pragma unroll
            for (int i = 0; i < 8; i++) {
                acc[i][0] += av[i]*bv.x; acc[i][1] += av[i]*bv.y;
                acc[i][2] += av[i]*bv.z; acc[i][3] += av[i]*bv.w;
            }
        }
        __syncthreads();
    }
#pragma unroll
    for (int i = 0; i < 8; i++) {
        int n = n0 + (i < 4 ? ty*4 + i : 64 + ty*4 + i - 4);
        float rinv = 1.f / rsum[(size_t)bh*Nn + n];
        float4 v = { acc[i][0]*rinv, acc[i][1]*rinv, acc[i][2]*rinv, acc[i][3]*rinv };
        *(float4*)(of + (size_t)(b*Nn + n)*Ii + h*DH + tx*4) = v;
    }
}

// ---------------- out_center partials: P[m,d] = sum_n (E[n,m]*f[n]) v1[n,d] ----------------
__global__ void __launch_bounds__(256)
attn_apply_center(const float* __restrict__ E, const float* __restrict__ v1,
                  const float* __restrict__ frow, float* __restrict__ ocp) {
    __shared__ float Ss[16][256];
    __shared__ float Vs[16][64];
    int bh = blockIdx.x, sp = blockIdx.y, b = bh >> 3, h = bh & 7;
    int t = threadIdx.x;
    int tm = (t & 31) * 8, td = (t >> 5) * 8;
    float acc[8][8] = {};
    int l_r = t >> 4, l_c = (t & 15) * 16;
    int lv_r = t >> 4, lv_c = (t & 15) * 4;
    int nbase = sp * 512;
    for (int n0 = 0; n0 < 512; n0 += 16) {
        int ng = nbase + n0 + l_r;
        const float* Sp = E + ((size_t)bh*Nn + ng) * Mm + l_c;
        float fv = frow[(size_t)bh*Nn + ng];
#pragma unroll
        for (int i = 0; i < 16; i += 4) {
            float4 v = *(const float4*)(Sp + i);
            Ss[l_r][l_c+i+0] = v.x * fv;
            Ss[l_r][l_c+i+1] = v.y * fv;
            Ss[l_r][l_c+i+2] = v.z * fv;
            Ss[l_r][l_c+i+3] = v.w * fv;
        }
        *(float4*)&Vs[lv_r][lv_c] =
            *(const float4*)(v1 + (size_t)(b*Nn + nbase + n0 + lv_r) * Ii + h*DH + lv_c);
        __syncthreads();
#pragma unroll
        for (int kk = 0; kk < 16; kk++) {
            float mr[8], dr[8];
            *(float4*)&mr[0] = *(const float4*)&Ss[kk][tm];
            *(float4*)&mr[4] = *(const float4*)&Ss[kk][tm+4];
            *(float4*)&dr[0] = *(const float4*)&Vs[kk][td];
            *(float4*)&dr[4] = *(const float4*)&Vs[kk][td+4];
#pragma unroll
            for (int i = 0; i < 8; i++)
#pragma unroll
                for (int j = 0; j < 8; j++)
                    acc[i][j] += mr[i] * dr[j];
        }
        __syncthreads();
    }
    float* op = ocp + ((size_t)(sp*BH + bh)) * Mm * DH;
#pragma unroll
    for (int i = 0; i < 8; i++)
#pragma unroll
        for (int j = 0; j < 8; j++)
            op[(size_t)(tm+i)*DH + td + j] = acc[i][j];
}

__global__ void __launch_bounds__(256)
oc_combine(const float* __restrict__ ocp, const float* __restrict__ csum,
           float* __restrict__ oc) {
    size_t idx = (size_t)blockIdx.x * 256 + threadIdx.x;
    int bh = (int)(idx >> 14);
    int r = (int)(idx & 16383);
    int m = r >> 6, d = r & 63;
    float s = 0.f;
#pragma unroll
    for (int sp = 0; sp < 8; sp++)
        s += ocp[((size_t)(sp*BH + bh)) * Mm * DH + (size_t)m*DH + d];
    int b = bh >> 3, h = bh & 7;
    oc[(size_t)(b*Mm + m) * Ii + h*DH + d] = s / csum[bh*Mm + m];
}

// ---------------- layernorm over last dim (256) ----------------
__global__ void __launch_bounds__(256)
layernorm(const float* __restrict__ x, const float* __restrict__ w,
          const float* __restrict__ b, float* __restrict__ y) {
    __shared__ float red[256];
    __shared__ float stat[2];
    int r = blockIdx.x, t = threadIdx.x;
    float v = x[(size_t)r*Dd + t];
    red[t] = v; __syncthreads();
    for (int o = 128; o; o >>= 1) { if (t < o) red[t] += red[t+o]; __syncthreads(); }
    if (t == 0) stat[0] = red[0] * (1.f/Dd);
    __syncthreads();
    float mu = stat[0];
    float dv = v - mu;
    red[t] = dv * dv; __syncthreads();
    for (int o = 128; o; o >>= 1) { if (t < o) red[t] += red[t+o]; __syncthreads(); }
    if (t == 0) stat[1] = rsqrtf(red[0] * (1.f/Dd) + EPS);
    __syncthreads();
    y[(size_t)r*Dd + t] = dv * stat[1] * w[t] + b[t];
}

// ---------------- launch ----------------
extern "C" void kernel_launch(void* const* d_in, const int* in_sizes, int n_in,
                              void* d_out, int out_size) {
    const float* feat       = (const float*)d_in[0];
    const float* center     = (const float*)d_in[1];
    const float* pos        = (const float*)d_in[2];
    const float* center_pos = (const float*)d_in[3];
    const float* Wq  = (const float*)d_in[4];
    const float* Wk  = (const float*)d_in[5];
    const float* Wv1 = (const float*)d_in[6];
    const float* Wv2 = (const float*)d_in[7];
    const float* Wo1 = (const float*)d_in[8];
    const float* Wo2 = (const float*)d_in[9];
    const float* ln1_w = (const float*)d_in[10];
    const float* ln1_b = (const float*)d_in[11];
    const float* ln2_w = (const float*)d_in[12];
    const float* ln2_b = (const float*)d_in[13];
    const float* f1W1 = (const float*)d_in[14];
    const float* f1W2 = (const float*)d_in[15];
    const float* f1b2 = (const float*)d_in[16];
    const float* f2W1 = (const float*)d_in[17];
    const float* f2W2 = (const float*)d_in[18];
    const float* f2b2 = (const float*)d_in[19];

    float* out_feat   = (float*)d_out;
    float* out_center = (float*)d_out + (size_t)Bb*Nn*Dd;

    float *posT,*q,*k,*v1,*v2,*E,*frow,*rsum,*pcsum,*csum,*of,*ocp,*oc,*pre,*prec,*xf,*xc,*hf,*hc;
    cudaGetSymbolAddress((void**)&posT, g_posT);
    cudaGetSymbolAddress((void**)&q,    g_q);
    cudaGetSymbolAddress((void**)&k,    g_k);
    cudaGetSymbolAddress((void**)&v1,   g_v1);
    cudaGetSymbolAddress((void**)&v2,   g_v2);
    cudaGetSymbolAddress((void**)&E,    g_E);
    cudaGetSymbolAddress((void**)&frow, g_f);
    cudaGetSymbolAddress((void**)&rsum, g_rsum);
    cudaGetSymbolAddress((void**)&pcsum,g_pcsum);
    cudaGetSymbolAddress((void**)&csum, g_csum);
    cudaGetSymbolAddress((void**)&of,   g_of);
    cudaGetSymbolAddress((void**)&ocp,  g_ocp);
    cudaGetSymbolAddress((void**)&oc,   g_oc);
    cudaGetSymbolAddress((void**)&pre,  g_pre);
    cudaGetSymbolAddress((void**)&prec, g_prec);
    cudaGetSymbolAddress((void**)&xf,   g_xf);
    cudaGetSymbolAddress((void**)&xc,   g_xc);
    cudaGetSymbolAddress((void**)&hf,   g_hf);
    cudaGetSymbolAddress((void**)&hc,   g_hc);

    transpose_pos<<<dim3(Dd/32, Nn/32, Bb), dim3(32,32)>>>(pos, posT);

    // projections (128x128 tiles)
    gemm128<1,0><<<dim3(Ii/128, Bb*Nn/128), 256>>>(feat, posT, Wq, nullptr, nullptr, q, Bb*Nn, Dd, Ii);
    gemm128<0,0><<<dim3(Ii/128, Bb*Nn/128), 256>>>(feat, nullptr, Wv1, nullptr, nullptr, v1, Bb*Nn, Dd, Ii);
    gemm128<1,0><<<dim3(Ii/128, Bb*Mm/128), 256>>>(center, center_pos, Wk, nullptr, nullptr, k, Bb*Mm, Dd, Ii);
    gemm128<0,0><<<dim3(Ii/128, Bb*Mm/128), 256>>>(center, nullptr, Wv2, nullptr, nullptr, v2, Bb*Mm, Dd, Ii);

    // fused scores + stats (E, f, rsum, col partials)
    attn_scores_fused<<<dim3(Nn/128, BH), 512>>>(q, k, E, frow, rsum, pcsum);
    csum_combine<<<BH, 256>>>(pcsum, csum);

    // attention applies
    attn_apply_feat<<<dim3(Nn/128, BH), 256>>>(E, v2, rsum, of);
    attn_apply_center<<<dim3(BH, 8), 256>>>(E, v1, frow, ocp);
    oc_combine<<<BH*Mm*DH/256, 256>>>(ocp, csum, oc);

    // feat path
    gemm128<0,1><<<dim3(Dd/128, Bb*Nn/128), 256>>>(of, nullptr, Wo1, feat, nullptr, pre, Bb*Nn, Ii, Dd);
    layernorm<<<Bb*Nn, 256>>>(pre, ln1_w, ln1_b, xf);
    gemm128<0,2><<<dim3(Dd/128, Bb*Nn/128), 256>>>(xf, nullptr, f1W1, nullptr, nullptr, hf, Bb*Nn, Dd, Dd);
    gemm128<0,3><<<dim3(Dd/128, Bb*Nn/128), 256>>>(hf, nullptr, f1W2, xf, f1b2, out_feat, Bb*Nn, Dd, Dd);

    // center path
    gemm128<0,1><<<dim3(Dd/128, Bb*Mm/128), 256>>>(oc, nullptr, Wo2, center, nullptr, prec, Bb*Mm, Ii, Dd);
    layernorm<<<Bb*Mm, 256>>>(prec, ln2_w, ln2_b, xc);
    gemm128<0,2><<<dim3(Dd/128, Bb*Mm/128), 256>>>(xc, nullptr, f2W1, nullptr, nullptr, hc, Bb*Mm, Dd, Dd);
    gemm128<0,3><<<dim3(Dd/128, Bb*Mm/128), 256>>>(hc, nullptr, f2W2, xc, f2b2, out_center, Bb*Mm, Dd, Dd);
}

// round 13
// speedup vs baseline: 1.5491x; 1.1962x over previous
#include <cuda_runtime.h>
#include <cuda_bf16.h>
#include <cstdint>

// ---------------- problem constants ----------------
#define Bb   8
#define Nn   4096
#define Mm   256
#define Dd   256
#define Ii   512
#define DH   64
#define BH   64
#define SCALE 0.125f
#define EPS   1e-5f

// ---------------- scratch ----------------
__device__ float g_posT[Bb*Nn*Dd];
__device__ float g_q  [Bb*Nn*Ii];
__device__ float g_k  [Bb*Mm*Ii];
__device__ float g_v1 [Bb*Nn*Ii];
__device__ float g_v2 [Bb*Mm*Ii];
__device__ float g_E  [(size_t)BH*Nn*Mm];     // exp(S - rowmax)
__device__ float g_f  [BH*Nn];                // exp(rowmax)
__device__ float g_rsum[BH*Nn];
__device__ float g_pcsum[32*BH*Mm];
__device__ float g_csum[BH*Mm];
__device__ float g_of [Bb*Nn*Ii];
__device__ float g_ocp[(size_t)8*BH*Mm*DH];
__device__ float g_oc [Bb*Mm*Ii];
__device__ float g_pre [Bb*Nn*Dd];
__device__ float g_prec[Bb*Mm*Dd];
__device__ float g_xf [Bb*Nn*Dd];
__device__ float g_xc [Bb*Mm*Dd];
__device__ float g_hf [Bb*Nn*Dd];
__device__ float g_hc [Bb*Mm*Dd];

// transposed + hi/lo-split weights (bf16), [N][K] layout
__device__ __nv_bfloat16 g_wqh[Ii*Dd],  g_wql[Ii*Dd];    // Wq^T   [512][256]
__device__ __nv_bfloat16 g_wv1h[Ii*Dd], g_wv1l[Ii*Dd];   // Wv1^T  [512][256]
__device__ __nv_bfloat16 g_wo1h[Dd*Ii], g_wo1l[Dd*Ii];   // Wo1^T  [256][512]
__device__ __nv_bfloat16 g_w1h[Dd*Dd],  g_w1l[Dd*Dd];    // f1W1^T [256][256]
__device__ __nv_bfloat16 g_w2h[Dd*Dd],  g_w2l[Dd*Dd];    // f1W2^T [256][256]

// ================= warp-mma helpers =================
__device__ __forceinline__ uint32_t smem_u32(const void* p) {
    uint32_t a;
    asm("{ .reg .u64 t; cvta.to.shared.u64 t, %1; cvt.u32.u64 %0, t; }" : "=r"(a) : "l"(p));
    return a;
}
__device__ __forceinline__ void ldm_x4(uint32_t* r, uint32_t addr) {
    asm volatile("ldmatrix.sync.aligned.m8n8.x4.shared.b16 {%0,%1,%2,%3}, [%4];"
        : "=r"(r[0]), "=r"(r[1]), "=r"(r[2]), "=r"(r[3]) : "r"(addr));
}
__device__ __forceinline__ void mma16816(float* d, const uint32_t* a, uint32_t b0, uint32_t b1) {
    asm volatile("mma.sync.aligned.m16n8k16.row.col.f32.bf16.bf16.f32 "
        "{%0,%1,%2,%3}, {%4,%5,%6,%7}, {%8,%9}, {%0,%1,%2,%3};"
        : "+f"(d[0]), "+f"(d[1]), "+f"(d[2]), "+f"(d[3])
        : "r"(a[0]), "r"(a[1]), "r"(a[2]), "r"(a[3]), "r"(b0), "r"(b1));
}
__device__ __forceinline__ uint32_t pack2bf(__nv_bfloat16 a, __nv_bfloat16 b) {
    return (uint32_t)__bfloat16_as_ushort(a) | ((uint32_t)__bfloat16_as_ushort(b) << 16);
}

#define AP 40   // padded smem row length in bf16 (80B: 16B-aligned, ldmatrix conflict-free)

// ---------------- warp-MMA GEMM: C[Mr,Nc] = op(A)[Mr,K] @ Bt^T, tile 128x128 ----------------
// Bt given as [Nc][K] bf16 hi/lo.  AMODE: 0 plain, 1 A+A2.  EPI: 0 none, 1 +Res, 2 relu, 3 +bias+Res
template<int AMODE, int EPI>
__global__ void __launch_bounds__(256)
gemm_mma(const float* __restrict__ A, const float* __restrict__ A2,
         const __nv_bfloat16* __restrict__ Bh, const __nv_bfloat16* __restrict__ Bl,
         const float* __restrict__ Res, const float* __restrict__ bias,
         float* __restrict__ C, int K, int Nc) {
    __shared__ __nv_bfloat16 sAh[128][AP], sAl[128][AP], sBh[128][AP], sBl[128][AP];
    int t = threadIdx.x, lane = t & 31, w = t >> 5;
    int wm = (w & 3) * 32, wn = (w >> 2) * 64;
    int row0 = blockIdx.y * 128, col0 = blockIdx.x * 128;
    float acc[2][8][4] = {};

    int ar = t >> 1, ac = (t & 1) * 16;          // 128 rows x 32 cols per chunk
    const float* Ap  = A  + (size_t)(row0 + ar) * K + ac;
    const float* A2p = AMODE ? (A2 + (size_t)(row0 + ar) * K + ac) : (const float*)0;
    const __nv_bfloat16* Bhp = Bh + (size_t)(col0 + ar) * K + ac;
    const __nv_bfloat16* Blp = Bl + (size_t)(col0 + ar) * K + ac;

    const uint32_t bAh = smem_u32(&sAh[0][0]), bAl = smem_u32(&sAl[0][0]);
    const uint32_t bBh = smem_u32(&sBh[0][0]), bBl = smem_u32(&sBl[0][0]);
    int lr = lane & 15, lc = (lane >> 4) << 3;   // ldmatrix row/col-half

    for (int kc = 0; kc < K; kc += 32) {
        // ---- stage A (fp32 -> bf16 hi/lo) ----
#pragma unroll
        for (int i = 0; i < 4; i++) {
            float4 v = *(const float4*)(Ap + kc + i * 4);
            if (AMODE) {
                float4 u = *(const float4*)(A2p + kc + i * 4);
                v.x += u.x; v.y += u.y; v.z += u.z; v.w += u.w;
            }
            __nv_bfloat16 h0 = __float2bfloat16_rn(v.x), h1 = __float2bfloat16_rn(v.y),
                          h2 = __float2bfloat16_rn(v.z), h3 = __float2bfloat16_rn(v.w);
            __nv_bfloat16 l0 = __float2bfloat16_rn(v.x - __bfloat162float(h0)),
                          l1 = __float2bfloat16_rn(v.y - __bfloat162float(h1)),
                          l2 = __float2bfloat16_rn(v.z - __bfloat162float(h2)),
                          l3 = __float2bfloat16_rn(v.w - __bfloat162float(h3));
            *(uint2*)&sAh[ar][ac + i*4] = make_uint2(pack2bf(h0, h1), pack2bf(h2, h3));
            *(uint2*)&sAl[ar][ac + i*4] = make_uint2(pack2bf(l0, l1), pack2bf(l2, l3));
        }
        // ---- stage B (already bf16 hi/lo) ----
        *(uint4*)&sBh[ar][ac]     = *(const uint4*)(Bhp + kc);
        *(uint4*)&sBh[ar][ac + 8] = *(const uint4*)(Bhp + kc + 8);
        *(uint4*)&sBl[ar][ac]     = *(const uint4*)(Blp + kc);
        *(uint4*)&sBl[ar][ac + 8] = *(const uint4*)(Blp + kc + 8);
        __syncthreads();

#pragma unroll
        for (int kk = 0; kk < 32; kk += 16) {
            uint32_t ah[2][4], al[2][4];
#pragma unroll
            for (int mt = 0; mt < 2; mt++) {
                uint32_t off = (uint32_t)((wm + mt*16 + lr) * AP + kk + lc) * 2;
                ldm_x4(ah[mt], bAh + off);
                ldm_x4(al[mt], bAl + off);
            }
            uint32_t bhf[4][4], blf[4][4];
#pragma unroll
            for (int nt = 0; nt < 4; nt++) {
                uint32_t off = (uint32_t)((wn + nt*16 + lr) * AP + kk + lc) * 2;
                ldm_x4(bhf[nt], bBh + off);
                ldm_x4(blf[nt], bBl + off);
            }
#pragma unroll
            for (int mt = 0; mt < 2; mt++)
#pragma unroll
                for (int nt = 0; nt < 4; nt++) {
                    // n-tile 2*nt   : B regs {r0, r2};  n-tile 2*nt+1 : {r1, r3}
                    mma16816(acc[mt][nt*2],   ah[mt], bhf[nt][0], bhf[nt][2]);
                    mma16816(acc[mt][nt*2],   ah[mt], blf[nt][0], blf[nt][2]);
                    mma16816(acc[mt][nt*2],   al[mt], bhf[nt][0], bhf[nt][2]);
                    mma16816(acc[mt][nt*2+1], ah[mt], bhf[nt][1], bhf[nt][3]);
                    mma16816(acc[mt][nt*2+1], ah[mt], blf[nt][1], blf[nt][3]);
                    mma16816(acc[mt][nt*2+1], al[mt], bhf[nt][1], bhf[nt][3]);
                }
        }
        __syncthreads();
    }

    // ---- epilogue: thread holds (row, col*2) pairs per 16x8 tile ----
    int gid = lane >> 2, tid4 = lane & 3;
#pragma unroll
    for (int mt = 0; mt < 2; mt++) {
#pragma unroll
        for (int half = 0; half < 2; half++) {
            int r = row0 + wm + mt*16 + gid + half*8;
#pragma unroll
            for (int nt = 0; nt < 8; nt++) {
                int c = col0 + wn + nt*8 + tid4*2;
                float2 v = { acc[mt][nt][half*2], acc[mt][nt][half*2 + 1] };
                if (EPI == 1 || EPI == 3) {
                    float2 rv = *(const float2*)(Res + (size_t)r*Nc + c);
                    v.x += rv.x; v.y += rv.y;
                }
                if (EPI == 3) {
                    float2 bb = *(const float2*)(bias + c);
                    v.x += bb.x; v.y += bb.y;
                }
                if (EPI == 2) { v.x = fmaxf(v.x, 0.f); v.y = fmaxf(v.y, 0.f); }
                *(float2*)(C + (size_t)r*Nc + c) = v;
            }
        }
    }
}

// ---------------- weight transpose + bf16 hi/lo split: W[K,N] -> Wt[N,K] ----------------
__global__ void __launch_bounds__(1024)
wtc(const float* __restrict__ W, __nv_bfloat16* __restrict__ Wh,
    __nv_bfloat16* __restrict__ Wl, int K, int N) {
    __shared__ float tile[32][33];
    int k0 = blockIdx.x * 32, n0 = blockIdx.y * 32;
    int tx = threadIdx.x, ty = threadIdx.y;
    tile[ty][tx] = W[(size_t)(k0 + ty) * N + n0 + tx];
    __syncthreads();
    float v = tile[tx][ty];
    __nv_bfloat16 h = __float2bfloat16_rn(v);
    __nv_bfloat16 l = __float2bfloat16_rn(v - __bfloat162float(h));
    Wh[(size_t)(n0 + ty) * K + k0 + tx] = h;
    Wl[(size_t)(n0 + ty) * K + k0 + tx] = l;
}

// ---------------- pos transpose: [B, D, N] -> [B, N, D] ----------------
__global__ void __launch_bounds__(1024)
transpose_pos(const float* __restrict__ pos, float* __restrict__ posT) {
    __shared__ float t[32][33];
    int b = blockIdx.z;
    int c0 = blockIdx.x * 32, n0 = blockIdx.y * 32;
    int tx = threadIdx.x, ty = threadIdx.y;
    t[ty][tx] = pos[(size_t)b*Dd*Nn + (size_t)(c0+ty)*Nn + n0 + tx];
    __syncthreads();
    posT[(size_t)b*Nn*Dd + (size_t)(n0+ty)*Dd + c0 + tx] = t[tx][ty];
}

// ---------------- SIMT 128x128 GEMM (center path) ----------------
template<int AMODE, int EPI>
__global__ void __launch_bounds__(256, 2)
gemm128(const float* __restrict__ A, const float* __restrict__ A2,
        const float* __restrict__ Bm, const float* __restrict__ Res,
        const float* __restrict__ bias, float* __restrict__ C,
        int Mr, int K, int Nc) {
    __shared__ float As[16][128];
    __shared__ float Bs[16][128];
    int t = threadIdx.x;
    int tx = t & 15, ty = t >> 4;
    int row0 = blockIdx.y * 128, col0 = blockIdx.x * 128;
    float acc[8][8] = {};

    int ar  = t >> 1;
    int akc = (t & 1) * 8;
    const float* Ap  = A  + (size_t)(row0 + ar) * K + akc;
    const float* A2p = A2 + (size_t)(row0 + ar) * K + akc;
    int br = t >> 4;
    int bc = (t & 15) * 8;
    const float* Bp = Bm + (size_t)br * Nc + col0 + bc;

    float4 pa0 = *(const float4*)(Ap);
    float4 pa1 = *(const float4*)(Ap + 4);
    if (AMODE) {
        float4 q0 = *(const float4*)(A2p), q1 = *(const float4*)(A2p + 4);
        pa0.x+=q0.x; pa0.y+=q0.y; pa0.z+=q0.z; pa0.w+=q0.w;
        pa1.x+=q1.x; pa1.y+=q1.y; pa1.z+=q1.z; pa1.w+=q1.w;
    }
    float4 pb0 = *(const float4*)(Bp);
    float4 pb1 = *(const float4*)(Bp + 4);

    for (int kc = 0; kc < K; kc += 16) {
        As[akc+0][ar]=pa0.x; As[akc+1][ar]=pa0.y; As[akc+2][ar]=pa0.z; As[akc+3][ar]=pa0.w;
        As[akc+4][ar]=pa1.x; As[akc+5][ar]=pa1.y; As[akc+6][ar]=pa1.z; As[akc+7][ar]=pa1.w;
        *(float4*)&Bs[br][bc]   = pb0;
        *(float4*)&Bs[br][bc+4] = pb1;
        __syncthreads();
        if (kc + 16 < K) {
            pa0 = *(const float4*)(Ap + kc + 16);
            pa1 = *(const float4*)(Ap + kc + 20);
            if (AMODE) {
                float4 q0 = *(const float4*)(A2p + kc + 16), q1 = *(const float4*)(A2p + kc + 20);
                pa0.x+=q0.x; pa0.y+=q0.y; pa0.z+=q0.z; pa0.w+=q0.w;
                pa1.x+=q1.x; pa1.y+=q1.y; pa1.z+=q1.z; pa1.w+=q1.w;
            }
            pb0 = *(const float4*)(Bp + (size_t)(kc + 16) * Nc);
            pb1 = *(const float4*)(Bp + (size_t)(kc + 16) * Nc + 4);
        }
#pragma unroll
        for (int k = 0; k < 16; k++) {
            float4 a0 = *(const float4*)&As[k][ty*4];
            float4 a1 = *(const float4*)&As[k][64+ty*4];
            float4 b0 = *(const float4*)&Bs[k][tx*4];
            float4 b1 = *(const float4*)&Bs[k][64+tx*4];
            float av[8] = {a0.x,a0.y,a0.z,a0.w,a1.x,a1.y,a1.z,a1.w};
            float bv[8] = {b0.x,b0.y,b0.z,b0.w,b1.x,b1.y,b1.z,b1.w};
#pragma unroll
            for (int i = 0; i < 8; i++)
#pragma unroll
                for (int j = 0; j < 8; j++)
                    acc[i][j] += av[i] * bv[j];
        }
        __syncthreads();
    }

#pragma unroll
    for (int i = 0; i < 8; i++) {
        int r = row0 + (i < 4 ? ty*4 + i : 64 + ty*4 + i - 4);
#pragma unroll
        for (int jh = 0; jh < 2; jh++) {
            int c = col0 + jh*64 + tx*4;
            float4 v = { acc[i][jh*4+0], acc[i][jh*4+1], acc[i][jh*4+2], acc[i][jh*4+3] };
            if (EPI == 1 || EPI == 3) {
                float4 rv = *(const float4*)(Res + (size_t)r*Nc + c);
                v.x += rv.x; v.y += rv.y; v.z += rv.z; v.w += rv.w;
            }
            if (EPI == 3) {
                float4 bb = *(const float4*)(bias + c);
                v.x += bb.x; v.y += bb.y; v.z += bb.z; v.w += bb.w;
            }
            if (EPI == 2) {
                v.x = fmaxf(v.x, 0.f); v.y = fmaxf(v.y, 0.f);
                v.z = fmaxf(v.z, 0.f); v.w = fmaxf(v.w, 0.f);
            }
            *(float4*)(C + (size_t)r*Nc + c) = v;
        }
    }
}

// ---------------- fused scores: E=exp(S-rmax), f=exp(rmax), rsum, col partial sums ----------------
__global__ void __launch_bounds__(512, 1)
attn_scores_fused(const float* __restrict__ q, const float* __restrict__ kk,
                  float* __restrict__ E, float* __restrict__ frow,
                  float* __restrict__ rsum, float* __restrict__ pcsum) {
    __shared__ float As[16][128];
    __shared__ float Bs[16][256];
    int bh = blockIdx.y, b = bh >> 3, h = bh & 7;
    int n0 = blockIdx.x * 128;
    int t = threadIdx.x, tx = t & 31, wy = t >> 5;
    float acc[8][8] = {};

    int ar  = t >> 2, akc = (t & 3) * 4;
    const float* qp = q + (size_t)(b*Nn + n0 + ar) * Ii + h*DH + akc;
    int br  = t >> 1, bkc = (t & 1) * 8;
    const float* kp = kk + (size_t)(b*Mm + br) * Ii + h*DH + bkc;

    float4 pa = *(const float4*)(qp);
    float4 pb0 = *(const float4*)(kp);
    float4 pb1 = *(const float4*)(kp + 4);

    for (int kc = 0; kc < DH; kc += 16) {
        As[akc+0][ar]=pa.x; As[akc+1][ar]=pa.y; As[akc+2][ar]=pa.z; As[akc+3][ar]=pa.w;
        Bs[bkc+0][br]=pb0.x; Bs[bkc+1][br]=pb0.y; Bs[bkc+2][br]=pb0.z; Bs[bkc+3][br]=pb0.w;
        Bs[bkc+4][br]=pb1.x; Bs[bkc+5][br]=pb1.y; Bs[bkc+6][br]=pb1.z; Bs[bkc+7][br]=pb1.w;
        __syncthreads();
        if (kc + 16 < DH) {
            pa  = *(const float4*)(qp + kc + 16);
            pb0 = *(const float4*)(kp + kc + 16);
            pb1 = *(const float4*)(kp + kc + 20);
        }
#pragma unroll
        for (int k = 0; k < 16; k++) {
            float4 a0 = *(const float4*)&As[k][wy*8];
            float4 a1 = *(const float4*)&As[k][wy*8+4];
            float4 b0 = *(const float4*)&Bs[k][tx*4];
            float4 b1 = *(const float4*)&Bs[k][128+tx*4];
            float av[8] = {a0.x,a0.y,a0.z,a0.w,a1.x,a1.y,a1.z,a1.w};
            float bv[8] = {b0.x,b0.y,b0.z,b0.w,b1.x,b1.y,b1.z,b1.w};
#pragma unroll
            for (int i = 0; i < 8; i++)
#pragma unroll
                for (int j = 0; j < 8; j++)
                    acc[i][j] += av[i] * bv[j];
        }
        __syncthreads();
    }

    float colp[8] = {};
    float* Ebase = E + (size_t)bh * Nn * Mm;
#pragma unroll
    for (int i = 0; i < 8; i++) {
        int n = n0 + wy*8 + i;
        float mx = -1e30f;
#pragma unroll
        for (int j = 0; j < 8; j++) { acc[i][j] *= SCALE; mx = fmaxf(mx, acc[i][j]); }
#pragma unroll
        for (int o = 16; o; o >>= 1) mx = fmaxf(mx, __shfl_xor_sync(0xffffffffu, mx, o));
        float s = 0.f;
#pragma unroll
        for (int j = 0; j < 8; j++) { acc[i][j] = __expf(acc[i][j] - mx); s += acc[i][j]; }
#pragma unroll
        for (int o = 16; o; o >>= 1) s += __shfl_xor_sync(0xffffffffu, s, o);
        float fi = __expf(mx);
        if (tx == 0) { frow[(size_t)bh*Nn + n] = fi; rsum[(size_t)bh*Nn + n] = s; }
#pragma unroll
        for (int j = 0; j < 8; j++) colp[j] += acc[i][j] * fi;
        float* Ep = Ebase + (size_t)n * Mm;
        float4 e0 = {acc[i][0], acc[i][1], acc[i][2], acc[i][3]};
        float4 e1 = {acc[i][4], acc[i][5], acc[i][6], acc[i][7]};
        *(float4*)(Ep + tx*4)       = e0;
        *(float4*)(Ep + 128 + tx*4) = e1;
    }

    float* red = &Bs[0][0];
    __syncthreads();
#pragma unroll
    for (int j = 0; j < 8; j++) {
        int col = (j < 4) ? tx*4 + j : 128 + tx*4 + (j - 4);
        red[wy*256 + col] = colp[j];
    }
    __syncthreads();
    if (t < 256) {
        float s = 0.f;
#pragma unroll
        for (int w = 0; w < 16; w++) s += red[w*256 + t];
        pcsum[((size_t)blockIdx.x * BH + bh) * Mm + t] = s;
    }
}

__global__ void __launch_bounds__(256)
csum_combine(const float* __restrict__ pcsum, float* __restrict__ csum) {
    int bh = blockIdx.x, m = threadIdx.x;
    float s = 0.f;
#pragma unroll
    for (int p = 0; p < 32; p++) s += pcsum[((size_t)p*BH + bh) * Mm + m];
    csum[bh*Mm + m] = s;
}

// ---------------- out_feat = (E @ v2) / rsum ----------------
__global__ void __launch_bounds__(256, 2)
attn_apply_feat(const float* __restrict__ E, const float* __restrict__ v2,
                const float* __restrict__ rsum, float* __restrict__ of) {
    __shared__ float Es[16][128];
    __shared__ float Vs[16][64];
    int bh = blockIdx.y, b = bh >> 3, h = bh & 7;
    int n0 = blockIdx.x * 128;
    int t = threadIdx.x, tx = t & 15, ty = t >> 4;
    float acc[8][4] = {};

    int er = t >> 1, emc = (t & 1) * 8;
    const float* Ep = E + ((size_t)bh*Nn + n0 + er) * Mm + emc;
    int vr = t >> 4, vc = (t & 15) * 4;
    const float* Vp = v2 + (size_t)(b*Mm + vr) * Ii + h*DH + vc;

    float4 pe0 = *(const float4*)(Ep);
    float4 pe1 = *(const float4*)(Ep + 4);
    float4 pv  = *(const float4*)(Vp);

    for (int mc = 0; mc < Mm; mc += 16) {
        Es[emc+0][er]=pe0.x; Es[emc+1][er]=pe0.y; Es[emc+2][er]=pe0.z; Es[emc+3][er]=pe0.w;
        Es[emc+4][er]=pe1.x; Es[emc+5][er]=pe1.y; Es[emc+6][er]=pe1.z; Es[emc+7][er]=pe1.w;
        *(float4*)&Vs[vr][vc] = pv;
        __syncthreads();
        if (mc + 16 < Mm) {
            pe0 = *(const float4*)(Ep + mc + 16);
            pe1 = *(const float4*)(Ep + mc + 20);
            pv  = *(const float4*)(Vp + (size_t)(mc + 16) * Ii);
        }
#pragma unroll
        for (int k = 0; k < 16; k++) {
            float4 a0 = *(const float4*)&Es[k][ty*4];
            float4 a1 = *(const float4*)&Es[k][64+ty*4];
            float4 bv = *(const float4*)&Vs[k][tx*4];
            float av[8] = {a0.x,a0.y,a0.z,a0.w,a1.x,a1.y,a1.z,a1.w};
#pragma unroll
            for (int i = 0; i < 8; i++) {
                acc[i][0] += av[i]*bv.x; acc[i][1] += av[i]*bv.y;
                acc[i][2] += av[i]*bv.z; acc[i][3] += av[i]*bv.w;
            }
        }
        __syncthreads();
    }
#pragma unroll
    for (int i = 0; i < 8; i++) {
        int n = n0 + (i < 4 ? ty*4 + i : 64 + ty*4 + i - 4);
        float rinv = 1.f / rsum[(size_t)bh*Nn + n];
        float4 v = { acc[i][0]*rinv, acc[i][1]*rinv, acc[i][2]*rinv, acc[i][3]*rinv };
        *(float4*)(of + (size_t)(b*Nn + n)*Ii + h*DH + tx*4) = v;
    }
}

// ---------------- out_center partials ----------------
__global__ void __launch_bounds__(256)
attn_apply_center(const float* __restrict__ E, const float* __restrict__ v1,
                  const float* __restrict__ frow, float* __restrict__ ocp) {
    __shared__ float Ss[16][256];
    __shared__ float Vs[16][64];
    int bh = blockIdx.x, sp = blockIdx.y, b = bh >> 3, h = bh & 7;
    int t = threadIdx.x;
    int tm = (t & 31) * 8, td = (t >> 5) * 8;
    float acc[8][8] = {};
    int l_r = t >> 4, l_c = (t & 15) * 16;
    int lv_r = t >> 4, lv_c = (t & 15) * 4;
    int nbase = sp * 512;
    for (int n0 = 0; n0 < 512; n0 += 16) {
        int ng = nbase + n0 + l_r;
        const float* Sp = E + ((size_t)bh*Nn + ng) * Mm + l_c;
        float fv = frow[(size_t)bh*Nn + ng];
#pragma unroll
        for (int i = 0; i < 16; i += 4) {
            float4 v = *(const float4*)(Sp + i);
            Ss[l_r][l_c+i+0] = v.x * fv;
            Ss[l_r][l_c+i+1] = v.y * fv;
            Ss[l_r][l_c+i+2] = v.z * fv;
            Ss[l_r][l_c+i+3] = v.w * fv;
        }
        *(float4*)&Vs[lv_r][lv_c] =
            *(const float4*)(v1 + (size_t)(b*Nn + nbase + n0 + lv_r) * Ii + h*DH + lv_c);
        __syncthreads();
#pragma unroll
        for (int kk = 0; kk < 16; kk++) {
            float mr[8], dr[8];
            *(float4*)&mr[0] = *(const float4*)&Ss[kk][tm];
            *(float4*)&mr[4] = *(const float4*)&Ss[kk][tm+4];
            *(float4*)&dr[0] = *(const float4*)&Vs[kk][td];
            *(float4*)&dr[4] = *(const float4*)&Vs[kk][td+4];
#pragma unroll
            for (int i = 0; i < 8; i++)
#pragma unroll
                for (int j = 0; j < 8; j++)
                    acc[i][j] += mr[i] * dr[j];
        }
        __syncthreads();
    }
    float* op = ocp + ((size_t)(sp*BH + bh)) * Mm * DH;
#pragma unroll
    for (int i = 0; i < 8; i++)
#pragma unroll
        for (int j = 0; j < 8; j++)
            op[(size_t)(tm+i)*DH + td + j] = acc[i][j];
}

__global__ void __launch_bounds__(256)
oc_combine(const float* __restrict__ ocp, const float* __restrict__ csum,
           float* __restrict__ oc) {
    size_t idx = (size_t)blockIdx.x * 256 + threadIdx.x;
    int bh = (int)(idx >> 14);
    int r = (int)(idx & 16383);
    int m = r >> 6, d = r & 63;
    float s = 0.f;
#pragma unroll
    for (int sp = 0; sp < 8; sp++)
        s += ocp[((size_t)(sp*BH + bh)) * Mm * DH + (size_t)m*DH + d];
    int b = bh >> 3, h = bh & 7;
    oc[(size_t)(b*Mm + m) * Ii + h*DH + d] = s / csum[bh*Mm + m];
}

// ---------------- layernorm over last dim (256) ----------------
__global__ void __launch_bounds__(256)
layernorm(const float* __restrict__ x, const float* __restrict__ w,
          const float* __restrict__ b, float* __restrict__ y) {
    __shared__ float red[256];
    __shared__ float stat[2];
    int r = blockIdx.x, t = threadIdx.x;
    float v = x[(size_t)r*Dd + t];
    red[t] = v; __syncthreads();
    for (int o = 128; o; o >>= 1) { if (t < o) red[t] += red[t+o]; __syncthreads(); }
    if (t == 0) stat[0] = red[0] * (1.f/Dd);
    __syncthreads();
    float mu = stat[0];
    float dv = v - mu;
    red[t] = dv * dv; __syncthreads();
    for (int o = 128; o; o >>= 1) { if (t < o) red[t] += red[t+o]; __syncthreads(); }
    if (t == 0) stat[1] = rsqrtf(red[0] * (1.f/Dd) + EPS);
    __syncthreads();
    y[(size_t)r*Dd + t] = dv * stat[1] * w[t] + b[t];
}

// ---------------- launch ----------------
extern "C" void kernel_launch(void* const* d_in, const int* in_sizes, int n_in,
                              void* d_out, int out_size) {
    const float* feat       = (const float*)d_in[0];
    const float* center     = (const float*)d_in[1];
    const float* pos        = (const float*)d_in[2];
    const float* center_pos = (const float*)d_in[3];
    const float* Wq  = (const float*)d_in[4];
    const float* Wk  = (const float*)d_in[5];
    const float* Wv1 = (const float*)d_in[6];
    const float* Wv2 = (const float*)d_in[7];
    const float* Wo1 = (const float*)d_in[8];
    const float* Wo2 = (const float*)d_in[9];
    const float* ln1_w = (const float*)d_in[10];
    const float* ln1_b = (const float*)d_in[11];
    const float* ln2_w = (const float*)d_in[12];
    const float* ln2_b = (const float*)d_in[13];
    const float* f1W1 = (const float*)d_in[14];
    const float* f1W2 = (const float*)d_in[15];
    const float* f1b2 = (const float*)d_in[16];
    const float* f2W1 = (const float*)d_in[17];
    const float* f2W2 = (const float*)d_in[18];
    const float* f2b2 = (const float*)d_in[19];

    float* out_feat   = (float*)d_out;
    float* out_center = (float*)d_out + (size_t)Bb*Nn*Dd;

    float *posT,*q,*k,*v1,*v2,*E,*frow,*rsum,*pcsum,*csum,*of,*ocp,*oc,*pre,*prec,*xf,*xc,*hf,*hc;
    cudaGetSymbolAddress((void**)&posT, g_posT);
    cudaGetSymbolAddress((void**)&q,    g_q);
    cudaGetSymbolAddress((void**)&k,    g_k);
    cudaGetSymbolAddress((void**)&v1,   g_v1);
    cudaGetSymbolAddress((void**)&v2,   g_v2);
    cudaGetSymbolAddress((void**)&E,    g_E);
    cudaGetSymbolAddress((void**)&frow, g_f);
    cudaGetSymbolAddress((void**)&rsum, g_rsum);
    cudaGetSymbolAddress((void**)&pcsum,g_pcsum);
    cudaGetSymbolAddress((void**)&csum, g_csum);
    cudaGetSymbolAddress((void**)&of,   g_of);
    cudaGetSymbolAddress((void**)&ocp,  g_ocp);
    cudaGetSymbolAddress((void**)&oc,   g_oc);
    cudaGetSymbolAddress((void**)&pre,  g_pre);
    cudaGetSymbolAddress((void**)&prec, g_prec);
    cudaGetSymbolAddress((void**)&xf,   g_xf);
    cudaGetSymbolAddress((void**)&xc,   g_xc);
    cudaGetSymbolAddress((void**)&hf,   g_hf);
    cudaGetSymbolAddress((void**)&hc,   g_hc);

    __nv_bfloat16 *wqh,*wql,*wv1h,*wv1l,*wo1h,*wo1l,*w1h,*w1l,*w2h,*w2l;
    cudaGetSymbolAddress((void**)&wqh,  g_wqh);
    cudaGetSymbolAddress((void**)&wql,  g_wql);
    cudaGetSymbolAddress((void**)&wv1h, g_wv1h);
    cudaGetSymbolAddress((void**)&wv1l, g_wv1l);
    cudaGetSymbolAddress((void**)&wo1h, g_wo1h);
    cudaGetSymbolAddress((void**)&wo1l, g_wo1l);
    cudaGetSymbolAddress((void**)&w1h,  g_w1h);
    cudaGetSymbolAddress((void**)&w1l,  g_w1l);
    cudaGetSymbolAddress((void**)&w2h,  g_w2h);
    cudaGetSymbolAddress((void**)&w2l,  g_w2l);

    transpose_pos<<<dim3(Dd/32, Nn/32, Bb), dim3(32,32)>>>(pos, posT);

    // weight transposes + bf16 hi/lo split
    wtc<<<dim3(Dd/32, Ii/32), dim3(32,32)>>>(Wq,   wqh,  wql,  Dd, Ii);
    wtc<<<dim3(Dd/32, Ii/32), dim3(32,32)>>>(Wv1,  wv1h, wv1l, Dd, Ii);
    wtc<<<dim3(Ii/32, Dd/32), dim3(32,32)>>>(Wo1,  wo1h, wo1l, Ii, Dd);
    wtc<<<dim3(Dd/32, Dd/32), dim3(32,32)>>>(f1W1, w1h,  w1l,  Dd, Dd);
    wtc<<<dim3(Dd/32, Dd/32), dim3(32,32)>>>(f1W2, w2h,  w2l,  Dd, Dd);

    // big feat-path projections on HMMA tensor path
    gemm_mma<1,0><<<dim3(Ii/128, Bb*Nn/128), 256>>>(feat, posT, wqh, wql, nullptr, nullptr, q,  Dd, Ii);
    gemm_mma<0,0><<<dim3(Ii/128, Bb*Nn/128), 256>>>(feat, nullptr, wv1h, wv1l, nullptr, nullptr, v1, Dd, Ii);

    // small center projections (SIMT)
    gemm128<1,0><<<dim3(Ii/128, Bb*Mm/128), 256>>>(center, center_pos, Wk, nullptr, nullptr, k, Bb*Mm, Dd, Ii);
    gemm128<0,0><<<dim3(Ii/128, Bb*Mm/128), 256>>>(center, nullptr, Wv2, nullptr, nullptr, v2, Bb*Mm, Dd, Ii);

    // fused scores + stats
    attn_scores_fused<<<dim3(Nn/128, BH), 512>>>(q, k, E, frow, rsum, pcsum);
    csum_combine<<<BH, 256>>>(pcsum, csum);

    // attention applies
    attn_apply_feat<<<dim3(Nn/128, BH), 256>>>(E, v2, rsum, of);
    attn_apply_center<<<dim3(BH, 8), 256>>>(E, v1, frow, ocp);
    oc_combine<<<BH*Mm*DH/256, 256>>>(ocp, csum, oc);

    // feat path (HMMA)
    gemm_mma<0,1><<<dim3(Dd/128, Bb*Nn/128), 256>>>(of, nullptr, wo1h, wo1l, feat, nullptr, pre, Ii, Dd);
    layernorm<<<Bb*Nn, 256>>>(pre, ln1_w, ln1_b, xf);
    gemm_mma<0,2><<<dim3(Dd/128, Bb*Nn/128), 256>>>(xf, nullptr, w1h, w1l, nullptr, nullptr, hf, Dd, Dd);
    gemm_mma<0,3><<<dim3(Dd/128, Bb*Nn/128), 256>>>(hf, nullptr, w2h, w2l, xf, f1b2, out_feat, Dd, Dd);

    // center path (SIMT, small)
    gemm128<0,1><<<dim3(Dd/128, Bb*Mm/128), 256>>>(oc, nullptr, Wo2, center, nullptr, prec, Bb*Mm, Ii, Dd);
    layernorm<<<Bb*Mm, 256>>>(prec, ln2_w, ln2_b, xc);
    gemm128<0,2><<<dim3(Dd/128, Bb*Mm/128), 256>>>(xc, nullptr, f2W1, nullptr, nullptr, hc, Bb*Mm, Dd, Dd);
    gemm128<0,3><<<dim3(Dd/128, Bb*Mm/128), 256>>>(hc, nullptr, f2W2, xc, f2b2, out_center, Bb*Mm, Dd, Dd);
}

// round 14
// speedup vs baseline: 1.6508x; 1.0656x over previous
#include <cuda_runtime.h>
#include <cuda_bf16.h>
#include <cstdint>

// ---------------- problem constants ----------------
#define Bb   8
#define Nn   4096
#define Mm   256
#define Dd   256
#define Ii   512
#define DH   64
#define BH   64
#define SCALE 0.125f
#define EPS   1e-5f

// ---------------- scratch ----------------
__device__ float g_posT[Bb*Nn*Dd];
__device__ float g_q  [Bb*Nn*Ii];
__device__ float g_k  [Bb*Mm*Ii];
__device__ float g_v1 [Bb*Nn*Ii];
__device__ float g_v2 [Bb*Mm*Ii];
__device__ float g_E  [(size_t)BH*Nn*Mm];     // exp(S - rowmax)
__device__ float g_f  [BH*Nn];                // exp(rowmax)
__device__ float g_rsum[BH*Nn];
__device__ float g_pcsum[32*BH*Mm];
__device__ float g_csum[BH*Mm];
__device__ float g_of [Bb*Nn*Ii];
__device__ float g_ocp[(size_t)8*BH*Mm*DH];
__device__ float g_oc [Bb*Mm*Ii];
__device__ float g_pre [Bb*Nn*Dd];
__device__ float g_prec[Bb*Mm*Dd];
__device__ float g_xf [Bb*Nn*Dd];
__device__ float g_xc [Bb*Mm*Dd];
__device__ float g_hf [Bb*Nn*Dd];
__device__ float g_hc [Bb*Mm*Dd];

// transposed + hi/lo-split weights (bf16), [N][K] layout
__device__ __nv_bfloat16 g_wqh[Ii*Dd],  g_wql[Ii*Dd];
__device__ __nv_bfloat16 g_wv1h[Ii*Dd], g_wv1l[Ii*Dd];
__device__ __nv_bfloat16 g_wo1h[Dd*Ii], g_wo1l[Dd*Ii];
__device__ __nv_bfloat16 g_w1h[Dd*Dd],  g_w1l[Dd*Dd];
__device__ __nv_bfloat16 g_w2h[Dd*Dd],  g_w2l[Dd*Dd];

// ================= warp-mma helpers =================
__device__ __forceinline__ uint32_t smem_u32(const void* p) {
    uint32_t a;
    asm("{ .reg .u64 t; cvta.to.shared.u64 t, %1; cvt.u32.u64 %0, t; }" : "=r"(a) : "l"(p));
    return a;
}
__device__ __forceinline__ void ldm_x4(uint32_t* r, uint32_t addr) {
    asm volatile("ldmatrix.sync.aligned.m8n8.x4.shared.b16 {%0,%1,%2,%3}, [%4];"
        : "=r"(r[0]), "=r"(r[1]), "=r"(r[2]), "=r"(r[3]) : "r"(addr));
}
__device__ __forceinline__ void mma16816(float* d, const uint32_t* a, uint32_t b0, uint32_t b1) {
    asm volatile("mma.sync.aligned.m16n8k16.row.col.f32.bf16.bf16.f32 "
        "{%0,%1,%2,%3}, {%4,%5,%6,%7}, {%8,%9}, {%0,%1,%2,%3};"
        : "+f"(d[0]), "+f"(d[1]), "+f"(d[2]), "+f"(d[3])
        : "r"(a[0]), "r"(a[1]), "r"(a[2]), "r"(a[3]), "r"(b0), "r"(b1));
}
__device__ __forceinline__ uint32_t pack2bf(__nv_bfloat16 a, __nv_bfloat16 b) {
    return (uint32_t)__bfloat16_as_ushort(a) | ((uint32_t)__bfloat16_as_ushort(b) << 16);
}
__device__ __forceinline__ void split4(float4 v, uint2& hi, uint2& lo) {
    __nv_bfloat16 h0 = __float2bfloat16_rn(v.x), h1 = __float2bfloat16_rn(v.y),
                  h2 = __float2bfloat16_rn(v.z), h3 = __float2bfloat16_rn(v.w);
    __nv_bfloat16 l0 = __float2bfloat16_rn(v.x - __bfloat162float(h0)),
                  l1 = __float2bfloat16_rn(v.y - __bfloat162float(h1)),
                  l2 = __float2bfloat16_rn(v.z - __bfloat162float(h2)),
                  l3 = __float2bfloat16_rn(v.w - __bfloat162float(h3));
    hi = make_uint2(pack2bf(h0, h1), pack2bf(h2, h3));
    lo = make_uint2(pack2bf(l0, l1), pack2bf(l2, l3));
}

#define AP 40   // padded row (bf16) for K=32 chunks
#define AP2 72  // padded row (bf16) for K=64 tiles

// ---------------- warp-MMA GEMM (feat path dense GEMMs) ----------------
template<int AMODE, int EPI>
__global__ void __launch_bounds__(256)
gemm_mma(const float* __restrict__ A, const float* __restrict__ A2,
         const __nv_bfloat16* __restrict__ Bh, const __nv_bfloat16* __restrict__ Bl,
         const float* __restrict__ Res, const float* __restrict__ bias,
         float* __restrict__ C, int K, int Nc) {
    __shared__ __nv_bfloat16 sAh[128][AP], sAl[128][AP], sBh[128][AP], sBl[128][AP];
    int t = threadIdx.x, lane = t & 31, w = t >> 5;
    int wm = (w & 3) * 32, wn = (w >> 2) * 64;
    int row0 = blockIdx.y * 128, col0 = blockIdx.x * 128;
    float acc[2][8][4] = {};

    int ar = t >> 1, ac = (t & 1) * 16;
    const float* Ap  = A  + (size_t)(row0 + ar) * K + ac;
    const float* A2p = AMODE ? (A2 + (size_t)(row0 + ar) * K + ac) : (const float*)0;
    const __nv_bfloat16* Bhp = Bh + (size_t)(col0 + ar) * K + ac;
    const __nv_bfloat16* Blp = Bl + (size_t)(col0 + ar) * K + ac;

    const uint32_t bAh = smem_u32(&sAh[0][0]), bAl = smem_u32(&sAl[0][0]);
    const uint32_t bBh = smem_u32(&sBh[0][0]), bBl = smem_u32(&sBl[0][0]);
    int lr = lane & 15, lc = (lane >> 4) << 3;

    for (int kc = 0; kc < K; kc += 32) {
#pragma unroll
        for (int i = 0; i < 4; i++) {
            float4 v = *(const float4*)(Ap + kc + i * 4);
            if (AMODE) {
                float4 u = *(const float4*)(A2p + kc + i * 4);
                v.x += u.x; v.y += u.y; v.z += u.z; v.w += u.w;
            }
            uint2 hi, lo; split4(v, hi, lo);
            *(uint2*)&sAh[ar][ac + i*4] = hi;
            *(uint2*)&sAl[ar][ac + i*4] = lo;
        }
        *(uint4*)&sBh[ar][ac]     = *(const uint4*)(Bhp + kc);
        *(uint4*)&sBh[ar][ac + 8] = *(const uint4*)(Bhp + kc + 8);
        *(uint4*)&sBl[ar][ac]     = *(const uint4*)(Blp + kc);
        *(uint4*)&sBl[ar][ac + 8] = *(const uint4*)(Blp + kc + 8);
        __syncthreads();

#pragma unroll
        for (int kk = 0; kk < 32; kk += 16) {
            uint32_t ah[2][4], al[2][4];
#pragma unroll
            for (int mt = 0; mt < 2; mt++) {
                uint32_t off = (uint32_t)((wm + mt*16 + lr) * AP + kk + lc) * 2;
                ldm_x4(ah[mt], bAh + off);
                ldm_x4(al[mt], bAl + off);
            }
            uint32_t bhf[4][4], blf[4][4];
#pragma unroll
            for (int nt = 0; nt < 4; nt++) {
                uint32_t off = (uint32_t)((wn + nt*16 + lr) * AP + kk + lc) * 2;
                ldm_x4(bhf[nt], bBh + off);
                ldm_x4(blf[nt], bBl + off);
            }
#pragma unroll
            for (int mt = 0; mt < 2; mt++)
#pragma unroll
                for (int nt = 0; nt < 4; nt++) {
                    mma16816(acc[mt][nt*2],   ah[mt], bhf[nt][0], bhf[nt][2]);
                    mma16816(acc[mt][nt*2],   ah[mt], blf[nt][0], blf[nt][2]);
                    mma16816(acc[mt][nt*2],   al[mt], bhf[nt][0], bhf[nt][2]);
                    mma16816(acc[mt][nt*2+1], ah[mt], bhf[nt][1], bhf[nt][3]);
                    mma16816(acc[mt][nt*2+1], ah[mt], blf[nt][1], blf[nt][3]);
                    mma16816(acc[mt][nt*2+1], al[mt], bhf[nt][1], bhf[nt][3]);
                }
        }
        __syncthreads();
    }

    int gid = lane >> 2, tid4 = lane & 3;
#pragma unroll
    for (int mt = 0; mt < 2; mt++) {
#pragma unroll
        for (int half = 0; half < 2; half++) {
            int r = row0 + wm + mt*16 + gid + half*8;
#pragma unroll
            for (int nt = 0; nt < 8; nt++) {
                int c = col0 + wn + nt*8 + tid4*2;
                float2 v = { acc[mt][nt][half*2], acc[mt][nt][half*2 + 1] };
                if (EPI == 1 || EPI == 3) {
                    float2 rv = *(const float2*)(Res + (size_t)r*Nc + c);
                    v.x += rv.x; v.y += rv.y;
                }
                if (EPI == 3) {
                    float2 bb = *(const float2*)(bias + c);
                    v.x += bb.x; v.y += bb.y;
                }
                if (EPI == 2) { v.x = fmaxf(v.x, 0.f); v.y = fmaxf(v.y, 0.f); }
                *(float2*)(C + (size_t)r*Nc + c) = v;
            }
        }
    }
}

// ---------------- HMMA fused scores: E, f, rsum, col partials ----------------
// tile 128n x 256m, K=64. 512 threads = 16 warps (4x4): wr=w>>2 rows, wc=w&3 cols.
#define SC_SMEM (110592)
__global__ void __launch_bounds__(512)
attn_scores_mma(const float* __restrict__ q, const float* __restrict__ kk,
                float* __restrict__ E, float* __restrict__ frow,
                float* __restrict__ rsum, float* __restrict__ pcsum) {
    extern __shared__ char sm[];
    __nv_bfloat16 (*sQh)[AP2] = (__nv_bfloat16(*)[AP2])(sm);
    __nv_bfloat16 (*sQl)[AP2] = (__nv_bfloat16(*)[AP2])(sm + 18432);
    __nv_bfloat16 (*sKh)[AP2] = (__nv_bfloat16(*)[AP2])(sm + 36864);
    __nv_bfloat16 (*sKl)[AP2] = (__nv_bfloat16(*)[AP2])(sm + 73728);
    float* redM  = (float*)sm;            // [4][128] aliased post-MMA
    float* redS  = (float*)(sm + 2048);   // [4][128]
    float* colred= (float*)(sm + 4096);   // [4][256]

    int bh = blockIdx.y, b = bh >> 3, h = bh & 7;
    int n0 = blockIdx.x * 128;
    int t = threadIdx.x, lane = t & 31, w = t >> 5;
    int wr = w >> 2, wc = w & 3;
    int lr = lane & 15, lc = (lane >> 4) << 3;
    int gid = lane >> 2, tid4 = lane & 3;
    float acc[2][8][4] = {};

    // stage q: 128 x 64 fp32 -> hi/lo
    {
        int qr = t >> 2, qc = (t & 3) * 16;
        const float* qp = q + (size_t)(b*Nn + n0 + qr) * Ii + h*DH + qc;
#pragma unroll
        for (int i = 0; i < 4; i++) {
            uint2 hi, lo; split4(*(const float4*)(qp + i*4), hi, lo);
            *(uint2*)&sQh[qr][qc + i*4] = hi;
            *(uint2*)&sQl[qr][qc + i*4] = lo;
        }
    }
    // stage k: 256 x 64
    {
        int kr = t >> 1, kc = (t & 1) * 32;
        const float* kp = kk + (size_t)(b*Mm + kr) * Ii + h*DH + kc;
#pragma unroll
        for (int i = 0; i < 8; i++) {
            uint2 hi, lo; split4(*(const float4*)(kp + i*4), hi, lo);
            *(uint2*)&sKh[kr][kc + i*4] = hi;
            *(uint2*)&sKl[kr][kc + i*4] = lo;
        }
    }
    __syncthreads();

    const uint32_t bQh = smem_u32(&sQh[0][0]), bQl = smem_u32(&sQl[0][0]);
    const uint32_t bKh = smem_u32(&sKh[0][0]), bKl = smem_u32(&sKl[0][0]);
#pragma unroll
    for (int kc = 0; kc < 64; kc += 16) {
        uint32_t ah[2][4], al[2][4];
#pragma unroll
        for (int mt = 0; mt < 2; mt++) {
            uint32_t off = (uint32_t)((wr*32 + mt*16 + lr) * AP2 + kc + lc) * 2;
            ldm_x4(ah[mt], bQh + off);
            ldm_x4(al[mt], bQl + off);
        }
        uint32_t bhf[4][4], blf[4][4];
#pragma unroll
        for (int nt = 0; nt < 4; nt++) {
            uint32_t off = (uint32_t)((wc*64 + nt*16 + lr) * AP2 + kc + lc) * 2;
            ldm_x4(bhf[nt], bKh + off);
            ldm_x4(blf[nt], bKl + off);
        }
#pragma unroll
        for (int mt = 0; mt < 2; mt++)
#pragma unroll
            for (int nt = 0; nt < 4; nt++) {
                mma16816(acc[mt][nt*2],   ah[mt], bhf[nt][0], bhf[nt][2]);
                mma16816(acc[mt][nt*2],   ah[mt], blf[nt][0], blf[nt][2]);
                mma16816(acc[mt][nt*2],   al[mt], bhf[nt][0], bhf[nt][2]);
                mma16816(acc[mt][nt*2+1], ah[mt], bhf[nt][1], bhf[nt][3]);
                mma16816(acc[mt][nt*2+1], ah[mt], blf[nt][1], blf[nt][3]);
                mma16816(acc[mt][nt*2+1], al[mt], bhf[nt][1], bhf[nt][3]);
            }
    }
    __syncthreads();   // smem now reusable for reductions

    // ---- softmax epilogue ----
    // combo c: mt=c>>1, half=c&1; row_local = wr*32 + mt*16 + half*8 + gid
    float vals[4][16];
    float gmax[4];
#pragma unroll
    for (int c = 0; c < 4; c++) {
        int mt = c >> 1, half = c & 1;
        float mx = -1e30f;
#pragma unroll
        for (int j = 0; j < 8; j++) {
            float v0 = acc[mt][j][half*2]     * SCALE;
            float v1 = acc[mt][j][half*2 + 1] * SCALE;
            vals[c][j*2] = v0; vals[c][j*2+1] = v1;
            mx = fmaxf(mx, fmaxf(v0, v1));
        }
        mx = fmaxf(mx, __shfl_xor_sync(0xffffffffu, mx, 1));
        mx = fmaxf(mx, __shfl_xor_sync(0xffffffffu, mx, 2));
        if (tid4 == 0) redM[wc*128 + wr*32 + mt*16 + half*8 + gid] = mx;
    }
    __syncthreads();
    float colacc[16];
#pragma unroll
    for (int i = 0; i < 16; i++) colacc[i] = 0.f;
#pragma unroll
    for (int c = 0; c < 4; c++) {
        int mt = c >> 1, half = c & 1;
        int rl = wr*32 + mt*16 + half*8 + gid;
        float mx = fmaxf(fmaxf(redM[rl], redM[128 + rl]),
                         fmaxf(redM[256 + rl], redM[384 + rl]));
        gmax[c] = mx;
        float s = 0.f;
        float fv = __expf(mx);
        float* Ep = E + ((size_t)bh*Nn + n0 + rl) * Mm;
#pragma unroll
        for (int j = 0; j < 8; j++) {
            float e0 = __expf(vals[c][j*2]   - mx);
            float e1 = __expf(vals[c][j*2+1] - mx);
            s += e0 + e1;
            colacc[j*2]   += e0 * fv;
            colacc[j*2+1] += e1 * fv;
            *(float2*)(Ep + wc*64 + j*8 + tid4*2) = make_float2(e0, e1);
        }
        s += __shfl_xor_sync(0xffffffffu, s, 1);
        s += __shfl_xor_sync(0xffffffffu, s, 2);
        if (tid4 == 0) redS[wc*128 + rl] = s;
    }
    __syncthreads();
#pragma unroll
    for (int c = 0; c < 4; c++) {
        int mt = c >> 1, half = c & 1;
        int rl = wr*32 + mt*16 + half*8 + gid;
        if (wc == 0 && tid4 == 0) {
            float s = redS[rl] + redS[128 + rl] + redS[256 + rl] + redS[384 + rl];
            rsum[(size_t)bh*Nn + n0 + rl] = s;
            frow[(size_t)bh*Nn + n0 + rl] = __expf(gmax[c]);
        }
    }
    // column partials: reduce colacc over gid (rows) via shfl, then over wr via smem
#pragma unroll
    for (int i = 0; i < 16; i++) {
        float v = colacc[i];
        v += __shfl_xor_sync(0xffffffffu, v, 4);
        v += __shfl_xor_sync(0xffffffffu, v, 8);
        v += __shfl_xor_sync(0xffffffffu, v, 16);
        colacc[i] = v;
    }
    if (gid == 0) {
#pragma unroll
        for (int j = 0; j < 8; j++) {
            colred[wr*256 + wc*64 + j*8 + tid4*2]     = colacc[j*2];
            colred[wr*256 + wc*64 + j*8 + tid4*2 + 1] = colacc[j*2+1];
        }
    }
    __syncthreads();
    if (t < 256) {
        float s = colred[t] + colred[256 + t] + colred[512 + t] + colred[768 + t];
        pcsum[((size_t)blockIdx.x * BH + bh) * Mm + t] = s;
    }
}

// ---------------- HMMA apply_feat: of = (E @ v2_h) / rsum ----------------
// tile 128n x 64d, K=256 in 32-chunks. 256 threads = 8 warps (4 rows x 2 cols).
__global__ void __launch_bounds__(256)
attn_apply_feat_mma(const float* __restrict__ E, const float* __restrict__ v2,
                    const float* __restrict__ rsum, float* __restrict__ of) {
    __shared__ __nv_bfloat16 sEh[128][AP], sEl[128][AP];
    __shared__ __nv_bfloat16 sVh[64][AP], sVl[64][AP];
    int bh = blockIdx.y, b = bh >> 3, h = bh & 7;
    int n0 = blockIdx.x * 128;
    int t = threadIdx.x, lane = t & 31, w = t >> 5;
    int wr = w & 3, wc = w >> 2;
    int lr = lane & 15, lc = (lane >> 4) << 3;
    int gid = lane >> 2, tid4 = lane & 3;
    float acc[2][4][4] = {};

    int er = t >> 1, ec = (t & 1) * 16;
    const float* Ep = E + ((size_t)bh*Nn + n0 + er) * Mm + ec;
    int vr = t >> 3, vcb = (t & 7) * 8;
    const float* Vp = v2 + (size_t)(b*Mm + vr) * Ii + h*DH + vcb;

    const uint32_t bEh = smem_u32(&sEh[0][0]), bEl = smem_u32(&sEl[0][0]);
    const uint32_t bVh = smem_u32(&sVh[0][0]), bVl = smem_u32(&sVl[0][0]);

    for (int mc = 0; mc < Mm; mc += 32) {
        // stage E (128 x 32) hi/lo
#pragma unroll
        for (int i = 0; i < 4; i++) {
            uint2 hi, lo; split4(*(const float4*)(Ep + mc + i*4), hi, lo);
            *(uint2*)&sEh[er][ec + i*4] = hi;
            *(uint2*)&sEl[er][ec + i*4] = lo;
        }
        // stage v2 chunk transposed: sV[d][m_local] (rows m = mc+vr)
#pragma unroll
        for (int i = 0; i < 8; i += 4) {
            float4 v = *(const float4*)(Vp + (size_t)mc * Ii + i);
            float vv[4] = {v.x, v.y, v.z, v.w};
#pragma unroll
            for (int j = 0; j < 4; j++) {
                int d = vcb + i + j;
                __nv_bfloat16 hh = __float2bfloat16_rn(vv[j]);
                sVh[d][vr] = hh;
                sVl[d][vr] = __float2bfloat16_rn(vv[j] - __bfloat162float(hh));
            }
        }
        __syncthreads();

#pragma unroll
        for (int kc2 = 0; kc2 < 32; kc2 += 16) {
            uint32_t ah[2][4], al[2][4];
#pragma unroll
            for (int mt = 0; mt < 2; mt++) {
                uint32_t off = (uint32_t)((wr*32 + mt*16 + lr) * AP + kc2 + lc) * 2;
                ldm_x4(ah[mt], bEh + off);
                ldm_x4(al[mt], bEl + off);
            }
            uint32_t bhf[2][4], blf[2][4];
#pragma unroll
            for (int nt = 0; nt < 2; nt++) {
                uint32_t off = (uint32_t)((wc*32 + nt*16 + lr) * AP + kc2 + lc) * 2;
                ldm_x4(bhf[nt], bVh + off);
                ldm_x4(blf[nt], bVl + off);
            }
#pragma unroll
            for (int mt = 0; mt < 2; mt++)
#pragma unroll
                for (int nt = 0; nt < 2; nt++) {
                    mma16816(acc[mt][nt*2],   ah[mt], bhf[nt][0], bhf[nt][2]);
                    mma16816(acc[mt][nt*2],   ah[mt], blf[nt][0], blf[nt][2]);
                    mma16816(acc[mt][nt*2],   al[mt], bhf[nt][0], bhf[nt][2]);
                    mma16816(acc[mt][nt*2+1], ah[mt], bhf[nt][1], bhf[nt][3]);
                    mma16816(acc[mt][nt*2+1], ah[mt], blf[nt][1], blf[nt][3]);
                    mma16816(acc[mt][nt*2+1], al[mt], bhf[nt][1], bhf[nt][3]);
                }
        }
        __syncthreads();
    }

#pragma unroll
    for (int mt = 0; mt < 2; mt++) {
#pragma unroll
        for (int half = 0; half < 2; half++) {
            int n = n0 + wr*32 + mt*16 + half*8 + gid;
            float rinv = 1.f / rsum[(size_t)bh*Nn + n];
#pragma unroll
            for (int j = 0; j < 4; j++) {
                int c = wc*32 + j*8 + tid4*2;
                float2 v = { acc[mt][j][half*2] * rinv, acc[mt][j][half*2 + 1] * rinv };
                *(float2*)(of + (size_t)(b*Nn + n)*Ii + h*DH + c) = v;
            }
        }
    }
}

// ---------------- weight transpose + bf16 hi/lo split ----------------
__global__ void __launch_bounds__(1024)
wtc(const float* __restrict__ W, __nv_bfloat16* __restrict__ Wh,
    __nv_bfloat16* __restrict__ Wl, int K, int N) {
    __shared__ float tile[32][33];
    int k0 = blockIdx.x * 32, n0 = blockIdx.y * 32;
    int tx = threadIdx.x, ty = threadIdx.y;
    tile[ty][tx] = W[(size_t)(k0 + ty) * N + n0 + tx];
    __syncthreads();
    float v = tile[tx][ty];
    __nv_bfloat16 h = __float2bfloat16_rn(v);
    __nv_bfloat16 l = __float2bfloat16_rn(v - __bfloat162float(h));
    Wh[(size_t)(n0 + ty) * K + k0 + tx] = h;
    Wl[(size_t)(n0 + ty) * K + k0 + tx] = l;
}

// ---------------- pos transpose ----------------
__global__ void __launch_bounds__(1024)
transpose_pos(const float* __restrict__ pos, float* __restrict__ posT) {
    __shared__ float t[32][33];
    int b = blockIdx.z;
    int c0 = blockIdx.x * 32, n0 = blockIdx.y * 32;
    int tx = threadIdx.x, ty = threadIdx.y;
    t[ty][tx] = pos[(size_t)b*Dd*Nn + (size_t)(c0+ty)*Nn + n0 + tx];
    __syncthreads();
    posT[(size_t)b*Nn*Dd + (size_t)(n0+ty)*Dd + c0 + tx] = t[tx][ty];
}

// ---------------- SIMT 128x128 GEMM (center path) ----------------
template<int AMODE, int EPI>
__global__ void __launch_bounds__(256, 2)
gemm128(const float* __restrict__ A, const float* __restrict__ A2,
        const float* __restrict__ Bm, const float* __restrict__ Res,
        const float* __restrict__ bias, float* __restrict__ C,
        int Mr, int K, int Nc) {
    __shared__ float As[16][128];
    __shared__ float Bs[16][128];
    int t = threadIdx.x;
    int tx = t & 15, ty = t >> 4;
    int row0 = blockIdx.y * 128, col0 = blockIdx.x * 128;
    float acc[8][8] = {};

    int ar  = t >> 1;
    int akc = (t & 1) * 8;
    const float* Ap  = A  + (size_t)(row0 + ar) * K + akc;
    const float* A2p = A2 + (size_t)(row0 + ar) * K + akc;
    int br = t >> 4;
    int bc = (t & 15) * 8;
    const float* Bp = Bm + (size_t)br * Nc + col0 + bc;

    float4 pa0 = *(const float4*)(Ap);
    float4 pa1 = *(const float4*)(Ap + 4);
    if (AMODE) {
        float4 q0 = *(const float4*)(A2p), q1 = *(const float4*)(A2p + 4);
        pa0.x+=q0.x; pa0.y+=q0.y; pa0.z+=q0.z; pa0.w+=q0.w;
        pa1.x+=q1.x; pa1.y+=q1.y; pa1.z+=q1.z; pa1.w+=q1.w;
    }
    float4 pb0 = *(const float4*)(Bp);
    float4 pb1 = *(const float4*)(Bp + 4);

    for (int kc = 0; kc < K; kc += 16) {
        As[akc+0][ar]=pa0.x; As[akc+1][ar]=pa0.y; As[akc+2][ar]=pa0.z; As[akc+3][ar]=pa0.w;
        As[akc+4][ar]=pa1.x; As[akc+5][ar]=pa1.y; As[akc+6][ar]=pa1.z; As[akc+7][ar]=pa1.w;
        *(float4*)&Bs[br][bc]   = pb0;
        *(float4*)&Bs[br][bc+4] = pb1;
        __syncthreads();
        if (kc + 16 < K) {
            pa0 = *(const float4*)(Ap + kc + 16);
            pa1 = *(const float4*)(Ap + kc + 20);
            if (AMODE) {
                float4 q0 = *(const float4*)(A2p + kc + 16), q1 = *(const float4*)(A2p + kc + 20);
                pa0.x+=q0.x; pa0.y+=q0.y; pa0.z+=q0.z; pa0.w+=q0.w;
                pa1.x+=q1.x; pa1.y+=q1.y; pa1.z+=q1.z; pa1.w+=q1.w;
            }
            pb0 = *(const float4*)(Bp + (size_t)(kc + 16) * Nc);
            pb1 = *(const float4*)(Bp + (size_t)(kc + 16) * Nc + 4);
        }
#pragma unroll
        for (int k = 0; k < 16; k++) {
            float4 a0 = *(const float4*)&As[k][ty*4];
            float4 a1 = *(const float4*)&As[k][64+ty*4];
            float4 b0 = *(const float4*)&Bs[k][tx*4];
            float4 b1 = *(const float4*)&Bs[k][64+tx*4];
            float av[8] = {a0.x,a0.y,a0.z,a0.w,a1.x,a1.y,a1.z,a1.w};
            float bv[8] = {b0.x,b0.y,b0.z,b0.w,b1.x,b1.y,b1.z,b1.w};
#pragma unroll
            for (int i = 0; i < 8; i++)
#pragma unroll
                for (int j = 0; j < 8; j++)
                    acc[i][j] += av[i] * bv[j];
        }
        __syncthreads();
    }

#pragma unroll
    for (int i = 0; i < 8; i++) {
        int r = row0 + (i < 4 ? ty*4 + i : 64 + ty*4 + i - 4);
#pragma unroll
        for (int jh = 0; jh < 2; jh++) {
            int c = col0 + jh*64 + tx*4;
            float4 v = { acc[i][jh*4+0], acc[i][jh*4+1], acc[i][jh*4+2], acc[i][jh*4+3] };
            if (EPI == 1 || EPI == 3) {
                float4 rv = *(const float4*)(Res + (size_t)r*Nc + c);
                v.x += rv.x; v.y += rv.y; v.z += rv.z; v.w += rv.w;
            }
            if (EPI == 3) {
                float4 bb = *(const float4*)(bias + c);
                v.x += bb.x; v.y += bb.y; v.z += bb.z; v.w += bb.w;
            }
            if (EPI == 2) {
                v.x = fmaxf(v.x, 0.f); v.y = fmaxf(v.y, 0.f);
                v.z = fmaxf(v.z, 0.f); v.w = fmaxf(v.w, 0.f);
            }
            *(float4*)(C + (size_t)r*Nc + c) = v;
        }
    }
}

__global__ void __launch_bounds__(256)
csum_combine(const float* __restrict__ pcsum, float* __restrict__ csum) {
    int bh = blockIdx.x, m = threadIdx.x;
    float s = 0.f;
#pragma unroll
    for (int p = 0; p < 32; p++) s += pcsum[((size_t)p*BH + bh) * Mm + m];
    csum[bh*Mm + m] = s;
}

// ---------------- out_center partials (SIMT) ----------------
__global__ void __launch_bounds__(256)
attn_apply_center(const float* __restrict__ E, const float* __restrict__ v1,
                  const float* __restrict__ frow, float* __restrict__ ocp) {
    __shared__ float Ss[16][256];
    __shared__ float Vs[16][64];
    int bh = blockIdx.x, sp = blockIdx.y, b = bh >> 3, h = bh & 7;
    int t = threadIdx.x;
    int tm = (t & 31) * 8, td = (t >> 5) * 8;
    float acc[8][8] = {};
    int l_r = t >> 4, l_c = (t & 15) * 16;
    int lv_r = t >> 4, lv_c = (t & 15) * 4;
    int nbase = sp * 512;
    for (int n0 = 0; n0 < 512; n0 += 16) {
        int ng = nbase + n0 + l_r;
        const float* Sp = E + ((size_t)bh*Nn + ng) * Mm + l_c;
        float fv = frow[(size_t)bh*Nn + ng];
#pragma unroll
        for (int i = 0; i < 16; i += 4) {
            float4 v = *(const float4*)(Sp + i);
            Ss[l_r][l_c+i+0] = v.x * fv;
            Ss[l_r][l_c+i+1] = v.y * fv;
            Ss[l_r][l_c+i+2] = v.z * fv;
            Ss[l_r][l_c+i+3] = v.w * fv;
        }
        *(float4*)&Vs[lv_r][lv_c] =
            *(const float4*)(v1 + (size_t)(b*Nn + nbase + n0 + lv_r) * Ii + h*DH + lv_c);
        __syncthreads();
#pragma unroll
        for (int kk = 0; kk < 16; kk++) {
            float mr[8], dr[8];
            *(float4*)&mr[0] = *(const float4*)&Ss[kk][tm];
            *(float4*)&mr[4] = *(const float4*)&Ss[kk][tm+4];
            *(float4*)&dr[0] = *(const float4*)&Vs[kk][td];
            *(float4*)&dr[4] = *(const float4*)&Vs[kk][td+4];
#pragma unroll
            for (int i = 0; i < 8; i++)
#pragma unroll
                for (int j = 0; j < 8; j++)
                    acc[i][j] += mr[i] * dr[j];
        }
        __syncthreads();
    }
    float* op = ocp + ((size_t)(sp*BH + bh)) * Mm * DH;
#pragma unroll
    for (int i = 0; i < 8; i++)
#pragma unroll
        for (int j = 0; j < 8; j++)
            op[(size_t)(tm+i)*DH + td + j] = acc[i][j];
}

__global__ void __launch_bounds__(256)
oc_combine(const float* __restrict__ ocp, const float* __restrict__ csum,
           float* __restrict__ oc) {
    size_t idx = (size_t)blockIdx.x * 256 + threadIdx.x;
    int bh = (int)(idx >> 14);
    int r = (int)(idx & 16383);
    int m = r >> 6, d = r & 63;
    float s = 0.f;
#pragma unroll
    for (int sp = 0; sp < 8; sp++)
        s += ocp[((size_t)(sp*BH + bh)) * Mm * DH + (size_t)m*DH + d];
    int b = bh >> 3, h = bh & 7;
    oc[(size_t)(b*Mm + m) * Ii + h*DH + d] = s / csum[bh*Mm + m];
}

// ---------------- layernorm ----------------
__global__ void __launch_bounds__(256)
layernorm(const float* __restrict__ x, const float* __restrict__ w,
          const float* __restrict__ b, float* __restrict__ y) {
    __shared__ float red[256];
    __shared__ float stat[2];
    int r = blockIdx.x, t = threadIdx.x;
    float v = x[(size_t)r*Dd + t];
    red[t] = v; __syncthreads();
    for (int o = 128; o; o >>= 1) { if (t < o) red[t] += red[t+o]; __syncthreads(); }
    if (t == 0) stat[0] = red[0] * (1.f/Dd);
    __syncthreads();
    float mu = stat[0];
    float dv = v - mu;
    red[t] = dv * dv; __syncthreads();
    for (int o = 128; o; o >>= 1) { if (t < o) red[t] += red[t+o]; __syncthreads(); }
    if (t == 0) stat[1] = rsqrtf(red[0] * (1.f/Dd) + EPS);
    __syncthreads();
    y[(size_t)r*Dd + t] = dv * stat[1] * w[t] + b[t];
}

// ---------------- launch ----------------
extern "C" void kernel_launch(void* const* d_in, const int* in_sizes, int n_in,
                              void* d_out, int out_size) {
    const float* feat       = (const float*)d_in[0];
    const float* center     = (const float*)d_in[1];
    const float* pos        = (const float*)d_in[2];
    const float* center_pos = (const float*)d_in[3];
    const float* Wq  = (const float*)d_in[4];
    const float* Wk  = (const float*)d_in[5];
    const float* Wv1 = (const float*)d_in[6];
    const float* Wv2 = (const float*)d_in[7];
    const float* Wo1 = (const float*)d_in[8];
    const float* Wo2 = (const float*)d_in[9];
    const float* ln1_w = (const float*)d_in[10];
    const float* ln1_b = (const float*)d_in[11];
    const float* ln2_w = (const float*)d_in[12];
    const float* ln2_b = (const float*)d_in[13];
    const float* f1W1 = (const float*)d_in[14];
    const float* f1W2 = (const float*)d_in[15];
    const float* f1b2 = (const float*)d_in[16];
    const float* f2W1 = (const float*)d_in[17];
    const float* f2W2 = (const float*)d_in[18];
    const float* f2b2 = (const float*)d_in[19];

    float* out_feat   = (float*)d_out;
    float* out_center = (float*)d_out + (size_t)Bb*Nn*Dd;

    float *posT,*q,*k,*v1,*v2,*E,*frow,*rsum,*pcsum,*csum,*of,*ocp,*oc,*pre,*prec,*xf,*xc,*hf,*hc;
    cudaGetSymbolAddress((void**)&posT, g_posT);
    cudaGetSymbolAddress((void**)&q,    g_q);
    cudaGetSymbolAddress((void**)&k,    g_k);
    cudaGetSymbolAddress((void**)&v1,   g_v1);
    cudaGetSymbolAddress((void**)&v2,   g_v2);
    cudaGetSymbolAddress((void**)&E,    g_E);
    cudaGetSymbolAddress((void**)&frow, g_f);
    cudaGetSymbolAddress((void**)&rsum, g_rsum);
    cudaGetSymbolAddress((void**)&pcsum,g_pcsum);
    cudaGetSymbolAddress((void**)&csum, g_csum);
    cudaGetSymbolAddress((void**)&of,   g_of);
    cudaGetSymbolAddress((void**)&ocp,  g_ocp);
    cudaGetSymbolAddress((void**)&oc,   g_oc);
    cudaGetSymbolAddress((void**)&pre,  g_pre);
    cudaGetSymbolAddress((void**)&prec, g_prec);
    cudaGetSymbolAddress((void**)&xf,   g_xf);
    cudaGetSymbolAddress((void**)&xc,   g_xc);
    cudaGetSymbolAddress((void**)&hf,   g_hf);
    cudaGetSymbolAddress((void**)&hc,   g_hc);

    __nv_bfloat16 *wqh,*wql,*wv1h,*wv1l,*wo1h,*wo1l,*w1h,*w1l,*w2h,*w2l;
    cudaGetSymbolAddress((void**)&wqh,  g_wqh);
    cudaGetSymbolAddress((void**)&wql,  g_wql);
    cudaGetSymbolAddress((void**)&wv1h, g_wv1h);
    cudaGetSymbolAddress((void**)&wv1l, g_wv1l);
    cudaGetSymbolAddress((void**)&wo1h, g_wo1h);
    cudaGetSymbolAddress((void**)&wo1l, g_wo1l);
    cudaGetSymbolAddress((void**)&w1h,  g_w1h);
    cudaGetSymbolAddress((void**)&w1l,  g_w1l);
    cudaGetSymbolAddress((void**)&w2h,  g_w2h);
    cudaGetSymbolAddress((void**)&w2l,  g_w2l);

    cudaFuncSetAttribute(attn_scores_mma, cudaFuncAttributeMaxDynamicSharedMemorySize, SC_SMEM);

    transpose_pos<<<dim3(Dd/32, Nn/32, Bb), dim3(32,32)>>>(pos, posT);

    wtc<<<dim3(Dd/32, Ii/32), dim3(32,32)>>>(Wq,   wqh,  wql,  Dd, Ii);
    wtc<<<dim3(Dd/32, Ii/32), dim3(32,32)>>>(Wv1,  wv1h, wv1l, Dd, Ii);
    wtc<<<dim3(Ii/32, Dd/32), dim3(32,32)>>>(Wo1,  wo1h, wo1l, Ii, Dd);
    wtc<<<dim3(Dd/32, Dd/32), dim3(32,32)>>>(f1W1, w1h,  w1l,  Dd, Dd);
    wtc<<<dim3(Dd/32, Dd/32), dim3(32,32)>>>(f1W2, w2h,  w2l,  Dd, Dd);

    gemm_mma<1,0><<<dim3(Ii/128, Bb*Nn/128), 256>>>(feat, posT, wqh, wql, nullptr, nullptr, q,  Dd, Ii);
    gemm_mma<0,0><<<dim3(Ii/128, Bb*Nn/128), 256>>>(feat, nullptr, wv1h, wv1l, nullptr, nullptr, v1, Dd, Ii);

    gemm128<1,0><<<dim3(Ii/128, Bb*Mm/128), 256>>>(center, center_pos, Wk, nullptr, nullptr, k, Bb*Mm, Dd, Ii);
    gemm128<0,0><<<dim3(Ii/128, Bb*Mm/128), 256>>>(center, nullptr, Wv2, nullptr, nullptr, v2, Bb*Mm, Dd, Ii);

    // HMMA fused scores + stats
    attn_scores_mma<<<dim3(Nn/128, BH), 512, SC_SMEM>>>(q, k, E, frow, rsum, pcsum);
    csum_combine<<<BH, 256>>>(pcsum, csum);

    // attention applies
    attn_apply_feat_mma<<<dim3(Nn/128, BH), 256>>>(E, v2, rsum, of);
    attn_apply_center<<<dim3(BH, 8), 256>>>(E, v1, frow, ocp);
    oc_combine<<<BH*Mm*DH/256, 256>>>(ocp, csum, oc);

    // feat path (HMMA)
    gemm_mma<0,1><<<dim3(Dd/128, Bb*Nn/128), 256>>>(of, nullptr, wo1h, wo1l, feat, nullptr, pre, Ii, Dd);
    layernorm<<<Bb*Nn, 256>>>(pre, ln1_w, ln1_b, xf);
    gemm_mma<0,2><<<dim3(Dd/128, Bb*Nn/128), 256>>>(xf, nullptr, w1h, w1l, nullptr, nullptr, hf, Dd, Dd);
    gemm_mma<0,3><<<dim3(Dd/128, Bb*Nn/128), 256>>>(hf, nullptr, w2h, w2l, xf, f1b2, out_feat, Dd, Dd);

    // center path (SIMT, small)
    gemm128<0,1><<<dim3(Dd/128, Bb*Mm/128), 256>>>(oc, nullptr, Wo2, center, nullptr, prec, Bb*Mm, Ii, Dd);
    layernorm<<<Bb*Mm, 256>>>(prec, ln2_w, ln2_b, xc);
    gemm128<0,2><<<dim3(Dd/128, Bb*Mm/128), 256>>>(xc, nullptr, f2W1, nullptr, nullptr, hc, Bb*Mm, Dd, Dd);
    gemm128<0,3><<<dim3(Dd/128, Bb*Mm/128), 256>>>(hc, nullptr, f2W2, xc, f2b2, out_center, Bb*Mm, Dd, Dd);
}